// round 10
// baseline (speedup 1.0000x reference)
#include <cuda_runtime.h>
#include <cuda_bf16.h>
#include <cstdint>
#include <math.h>

#define BATCH 64
#define NCAPS 2048
#define IDIM 16
#define DOUT 256
#define LK 32

typedef unsigned int u32;
typedef unsigned long long u64;

__device__ float g_u[(size_t)BATCH * NCAPS * DOUT];   // 134 MB
__device__ float g_C[(size_t)BATCH * DOUT * DOUT];    // 16 MB (lower triangle valid)

// ---------------------------------------------------------------------------
// Stage 1: u[b,c,o] = sum_i x[b,c,i] * w[c,i,o]
// ---------------------------------------------------------------------------
__global__ void k_u(const float* __restrict__ x, const float* __restrict__ w) {
    const int c = blockIdx.x;
    const int o = threadIdx.x;

    __shared__ __align__(16) float Xs[BATCH * IDIM];

    float W[IDIM];
#pragma unroll
    for (int i = 0; i < IDIM; ++i)
        W[i] = w[((size_t)c * IDIM + i) * DOUT + o];

    for (int l = o; l < BATCH * IDIM; l += 256) {
        int bb = l >> 4, ii = l & 15;
        Xs[l] = x[((size_t)bb * NCAPS + c) * IDIM + ii];
    }
    __syncthreads();

    for (int bb = 0; bb < BATCH; ++bb) {
        const float4 x0 = *(const float4*)&Xs[bb * IDIM + 0];
        const float4 x1 = *(const float4*)&Xs[bb * IDIM + 4];
        const float4 x2 = *(const float4*)&Xs[bb * IDIM + 8];
        const float4 x3 = *(const float4*)&Xs[bb * IDIM + 12];
        float a0 = x0.x * W[0], a1 = x0.y * W[1], a2 = x0.z * W[2], a3 = x0.w * W[3];
        a0 = fmaf(x1.x, W[4], a0);  a1 = fmaf(x1.y, W[5], a1);
        a2 = fmaf(x1.z, W[6], a2);  a3 = fmaf(x1.w, W[7], a3);
        a0 = fmaf(x2.x, W[8], a0);  a1 = fmaf(x2.y, W[9], a1);
        a2 = fmaf(x2.z, W[10], a2); a3 = fmaf(x2.w, W[11], a3);
        a0 = fmaf(x3.x, W[12], a0); a1 = fmaf(x3.y, W[13], a1);
        a2 = fmaf(x3.z, W[14], a2); a3 = fmaf(x3.w, W[15], a3);
        g_u[((size_t)bb * NCAPS + c) * DOUT + o] = (a0 + a1) + (a2 + a3);
    }
}

// ---------------------------------------------------------------------------
// Stage 2: lower-triangle tiles of C_b = U_b^T U_b (FFMA2, cp.async dbuf)
// ---------------------------------------------------------------------------
__device__ __forceinline__ void cp16(u32 saddr, const float* g) {
    asm volatile("cp.async.ca.shared.global [%0], [%1], 16;\n" :: "r"(saddr), "l"(g));
}
__device__ __forceinline__ u64 dupf(float f) {
    u64 r;
    asm("mov.b64 %0, {%1, %1};" : "=l"(r) : "f"(f));
    return r;
}
__device__ __forceinline__ void ffma2(u64& acc, u64 a, u64 b) {
    asm("fma.rn.f32x2 %0, %1, %2, %0;" : "+l"(acc) : "l"(a), "l"(b));
}

__device__ __forceinline__ void sy_load(u32 sA, u32 sB,
                                        const float* Ub, int kc, int buf,
                                        int dbase, int ebase, bool diag, int tid) {
#pragma unroll
    for (int q = 0; q < 4; ++q) {
        int idx = q * 64 + tid;
        int r = idx >> 4;
        int c4 = (idx & 15) << 2;
        const float* srow = Ub + (size_t)(kc + r) * DOUT;
        u32 so = (u32)((buf * 1024 + r * 64 + c4) * 4);
        cp16(sA + so, srow + dbase + c4);
        if (!diag) cp16(sB + so, srow + ebase + c4);
    }
}

__global__ __launch_bounds__(64, 6) void k_syrk() {
    const int p = blockIdx.x;
    const int b = blockIdx.y;

    int dt, et;
    if (p < 1)      { dt = 0; et = 0; }
    else if (p < 3) { dt = 1; et = p - 1; }
    else if (p < 6) { dt = 2; et = p - 3; }
    else            { dt = 3; et = p - 6; }
    const bool diag = (dt == et);

    const int tid = threadIdx.x;
    const int tx = tid & 7, ty = tid >> 3;

    __shared__ __align__(16) float As[2][16][64];
    __shared__ __align__(16) float Bs[2][16][64];

    const float* Ub = g_u + (size_t)b * NCAPS * DOUT;
    const int dbase = dt * 64, ebase = et * 64;

    u64 acc[4][8];
#pragma unroll
    for (int i = 0; i < 4; ++i)
#pragma unroll
        for (int j = 0; j < 8; ++j) acc[i][j] = 0ull;

    u32 sA = (u32)__cvta_generic_to_shared(&As[0][0][0]);
    u32 sB = (u32)__cvta_generic_to_shared(&Bs[0][0][0]);

    sy_load(sA, sB, Ub, 0, 0, dbase, ebase, diag, tid);
    asm volatile("cp.async.commit_group;\n");

    for (int chunk = 0; chunk < NCAPS / 16; ++chunk) {
        const int buf = chunk & 1;
        if (chunk + 1 < NCAPS / 16) {
            sy_load(sA, sB, Ub, (chunk + 1) * 16, buf ^ 1, dbase, ebase, diag, tid);
            asm volatile("cp.async.commit_group;\n");
            asm volatile("cp.async.wait_group 1;\n");
        } else {
            asm volatile("cp.async.wait_group 0;\n");
        }
        __syncthreads();

#pragma unroll
        for (int kk = 0; kk < 16; ++kk) {
            ulonglong2 a01 = *(const ulonglong2*)&As[buf][kk][ty * 8];
            ulonglong2 a23 = *(const ulonglong2*)&As[buf][kk][ty * 8 + 4];
            const float* bp = diag ? &As[buf][kk][tx * 8] : &Bs[buf][kk][tx * 8];
            float4 bl = *(const float4*)bp;
            float4 bh = *(const float4*)(bp + 4);
            u64 bd[8];
            bd[0] = dupf(bl.x); bd[1] = dupf(bl.y); bd[2] = dupf(bl.z); bd[3] = dupf(bl.w);
            bd[4] = dupf(bh.x); bd[5] = dupf(bh.y); bd[6] = dupf(bh.z); bd[7] = dupf(bh.w);
            u64 ap[4] = {a01.x, a01.y, a23.x, a23.y};
#pragma unroll
            for (int ip = 0; ip < 4; ++ip)
#pragma unroll
                for (int j = 0; j < 8; ++j)
                    ffma2(acc[ip][j], ap[ip], bd[j]);
        }
        __syncthreads();
    }

    float* Cb = g_C + (size_t)b * DOUT * DOUT;
#pragma unroll
    for (int ip = 0; ip < 4; ++ip) {
        int d0 = dbase + ty * 8 + 2 * ip;
#pragma unroll
        for (int j = 0; j < 8; ++j) {
            float2 val = *(float2*)&acc[ip][j];
            int e = ebase + tx * 8 + j;
            Cb[d0 * DOUT + e] = val.x;
            Cb[(d0 + 1) * DOUT + e] = val.y;
        }
    }
}

// ---------------------------------------------------------------------------
// Stage 3: Lanczos(K=32) estimator + Chebyshev polish with residual exit.
// 512 threads; C as 36 swizzled 32x32 blocks; conflict-free matvec.
// ---------------------------------------------------------------------------
#define NBLK 36
#define BLK_FLOATS 1024
#define NW 16
#define Y2S_STRIDE 264
#define EIG_SMEM_FLOATS (NBLK * BLK_FLOATS + 2 * 256 + 64 + NW * Y2S_STRIDE \
                         + LK * 256 + 3 * 64)
#define EIG_SMEM_BYTES (EIG_SMEM_FLOATS * 4)

__device__ const unsigned char SB_R[NBLK] = {
    0, 1,1, 2,2,2, 3,3,3,3, 4,4,4,4,4, 5,5,5,5,5,5,
    6,6,6,6,6,6,6, 7,7,7,7,7,7,7,7 };
__device__ const unsigned char SB_C[NBLK] = {
    0, 0,1, 0,1,2, 0,1,2,3, 0,1,2,3,4, 0,1,2,3,4,5,
    0,1,2,3,4,5,6, 0,1,2,3,4,5,6,7 };

__device__ const unsigned char UNITS[64] = {
    0, 32, 36, 64, 68, 72, 96, 100, 104, 108, 128, 132, 136, 140, 144, 160,
    164, 168, 172, 176, 180, 192, 196, 200, 204, 208, 212, 216, 224, 228, 232, 236,
    240, 244, 248, 252,
    33, 65, 69, 97, 101, 105, 129, 133, 137, 141, 161, 165, 169, 173, 177, 193,
    197, 201, 205, 209, 213, 225, 229, 233, 237, 241, 245, 249 };

__device__ __forceinline__ int sw_off(int r, int c) {
    return r * 32 + ((((c >> 2) ^ (r & 7)) << 2) | (c & 3));
}

__device__ __forceinline__ float warpSum(float v) {
#pragma unroll
    for (int o = 16; o; o >>= 1) v += __shfl_xor_sync(0xffffffffu, v, o);
    return v;
}
__device__ float blockSum(float val, float* red, int t) {
    val = warpSum(val);
    if ((t & 31) == 0) red[t >> 5] = val;
    __syncthreads();
    if (t < 32) {
        float x = (t < NW) ? red[t] : 0.0f;
        x = warpSum(x);
        if (t == 0) red[32] = x;
    }
    __syncthreads();
    float r = red[32];
    __syncthreads();
    return r;
}
__device__ float blockMax(float val, float* red, int t) {
#pragma unroll
    for (int o = 16; o; o >>= 1) val = fmaxf(val, __shfl_xor_sync(0xffffffffu, val, o));
    if ((t & 31) == 0) red[t >> 5] = val;
    __syncthreads();
    if (t < 32) {
        float x = (t < NW) ? red[t] : -1.0f;
#pragma unroll
        for (int o = 16; o; o >>= 1) x = fmaxf(x, __shfl_xor_sync(0xffffffffu, x, o));
        if (t == 0) red[32] = x;
    }
    __syncthreads();
    float r = red[32];
    __syncthreads();
    return r;
}
__device__ int blockMinInt(int val, float* redf, int t) {
    int* red = (int*)redf;
#pragma unroll
    for (int o = 16; o; o >>= 1) val = min(val, __shfl_xor_sync(0xffffffffu, val, o));
    if ((t & 31) == 0) red[t >> 5] = val;
    __syncthreads();
    if (t < 32) {
        int x = (t < NW) ? red[t] : 0x7fffffff;
#pragma unroll
        for (int o = 16; o; o >>= 1) x = min(x, __shfl_xor_sync(0xffffffffu, x, o));
        if (t == 0) red[32] = x;
    }
    __syncthreads();
    int r = red[32];
    __syncthreads();
    return r;
}

// y[t] = (C v)[t] for t<256. One internal __syncthreads.
__device__ __forceinline__ float symMatvecB(const float* __restrict__ blocks,
                                            const float* __restrict__ v,
                                            float* __restrict__ y2s,
                                            int t) {
    const int l = t & 31, w = t >> 5;
    float* myp = y2s + w * Y2S_STRIDE;

#pragma unroll
    for (int k = 0; k < 8; ++k) myp[32 * k + l] = 0.0f;

#pragma unroll
    for (int q = 0; q < 4; ++q) {
        const int enc = UNITS[w + 16 * q];
        const int R = enc >> 5, C = (enc >> 2) & 7, type = enc & 1;
        const float* blk = blocks + (R * (R + 1) / 2 + C) * BLK_FLOATS;
        if (type == 0) {
            const float4* vq = (const float4*)(v + 32 * C);
            const float* bl = blk + l * 32;
            const int lx = l & 7;
            float a0 = 0.f, a1 = 0.f, a2 = 0.f, a3 = 0.f;
#pragma unroll
            for (int qq = 0; qq < 8; ++qq) {
                float4 a = *(const float4*)(bl + ((qq ^ lx) << 2));
                float4 vv = vq[qq];
                a0 = fmaf(a.x, vv.x, a0);
                a1 = fmaf(a.y, vv.y, a1);
                a2 = fmaf(a.z, vv.z, a2);
                a3 = fmaf(a.w, vv.w, a3);
            }
            myp[32 * R + l] += (a0 + a1) + (a2 + a3);
        } else {
            const int hi = l >> 2, lo = l & 3;
            const float* vb = v + 32 * R;
            float a0 = 0.f, a1 = 0.f, a2 = 0.f, a3 = 0.f;
#pragma unroll
            for (int rq = 0; rq < 8; ++rq) {
                float4 vv = *(const float4*)(vb + 4 * rq);
                const float* base = blk + rq * 128;
                a0 = fmaf(base[       (((hi ^ ((4 * rq)     & 7)) << 2) | lo)], vv.x, a0);
                a1 = fmaf(base[32  + (((hi ^ ((4 * rq + 1) & 7)) << 2) | lo)], vv.y, a1);
                a2 = fmaf(base[64  + (((hi ^ ((4 * rq + 2) & 7)) << 2) | lo)], vv.z, a2);
                a3 = fmaf(base[96  + (((hi ^ ((4 * rq + 3) & 7)) << 2) | lo)], vv.w, a3);
            }
            myp[32 * C + l] += (a0 + a1) + (a2 + a3);
        }
    }
    __syncthreads();

    float y = 0.f;
    if (t < 256) {
#pragma unroll
        for (int ww = 0; ww < NW; ++ww) y += y2s[ww * Y2S_STRIDE + t];
    }
    return y;
}

// Sturm count of eigenvalues of T (alphas, betas, size k) below x.
__device__ __forceinline__ int sturmCount(const float* alphas, const float* betas,
                                          int k, float x) {
    int cnt = 0;
    float d = alphas[0] - x;
    if (d < 0.0f) cnt++;
    for (int i = 1; i < k; ++i) {
        float dd = (fabsf(d) < 1e-22f) ? ((d < 0.0f) ? -1e-22f : 1e-22f) : d;
        d = alphas[i] - x - betas[i - 1] * betas[i - 1] / dd;
        if (d < 0.0f) cnt++;
    }
    return cnt;
}

__global__ __launch_bounds__(512, 1) void k_eig(float* __restrict__ out) {
    extern __shared__ __align__(16) float sm[];
    float* blocks = sm;                          // 36 * 1024
    float* v   = sm + NBLK * BLK_FLOATS;         // 256
    float* vp  = v + 256;                        // 256
    float* red = vp + 256;                       // 64
    float* y2s = red + 64;                       // 16 * 264 (also solver scratch)
    float* Vs  = y2s + NW * Y2S_STRIDE;          // LK * 256
    float* alphas = Vs + LK * 256;               // 64
    float* betas  = alphas + 64;                 // 64
    float* yv     = betas + 64;                  // 64

    const int b = blockIdx.x;
    const int t = threadIdx.x;
    const bool act = (t < 256);
    const float* Cb = g_C + (size_t)b * DOUT * DOUT;

    // Load 36 blocks; diag blocks mirrored to full. Swizzled store.
    for (int s = 0; s < NBLK; ++s) {
        const int R = SB_R[s], C = SB_C[s];
        float* dst = blocks + s * BLK_FLOATS;
#pragma unroll
        for (int k = 0; k < 2; ++k) {
            int idx = k * 512 + t;
            int r = idx >> 5, c = idx & 31;
            float val;
            if (R > C || c <= r) val = Cb[(32 * R + r) * DOUT + 32 * C + c];
            else                 val = Cb[(32 * C + c) * DOUT + 32 * R + r];
            dst[sw_off(r, c)] = val;
        }
    }
    if (act) { v[t] = Cb[t * DOUT]; vp[t] = 0.0f; }
    __syncthreads();

    {
        float n2 = blockSum(act ? v[t] * v[t] : 0.0f, red, t);
        if (act) v[t] *= rsqrtf(fmaxf(n2, 1e-30f));
    }
    __syncthreads();

    // ---- Lanczos estimator (K=32, basis in smem) ----
    float beta_prev = 0.0f;
    int kEff = 0;
    for (int j = 0; j < LK; ++j) {
        if (act) Vs[j * 256 + t] = v[t];
        float Cv = symMatvecB(blocks, v, y2s, t);
        float wv = act ? (Cv - beta_prev * vp[t]) : 0.0f;
        float alpha = blockSum(act ? v[t] * wv : 0.0f, red, t);
        if (act) wv -= alpha * v[t];
        float b2 = blockSum(wv * wv, red, t);
        if (t == 0) alphas[j] = alpha;
        kEff = j + 1;
        if (b2 < 1e-12f * alpha * alpha) break;
        float beta = sqrtf(b2);
        if (t == 0) betas[j] = beta;
        if (act) {
            vp[t] = v[t];
            v[t] = wv * (1.0f / beta);
        }
        beta_prev = beta;
        __syncthreads();
    }
    __syncthreads();

    // ---- Tridiag: lambda1, lambda2, Ritz weights (thread 0) ----
    if (t == 0) {
        const int k = kEff;
        float lo = alphas[0], hi = alphas[0];
        for (int i = 0; i < k; ++i) {
            float bl = (i > 0) ? fabsf(betas[i - 1]) : 0.0f;
            float br = (i < k - 1) ? fabsf(betas[i]) : 0.0f;
            lo = fmaxf(lo, alphas[i]);
            hi = fmaxf(hi, alphas[i] + bl + br);
        }
        // lambda1
        float l1lo = lo, l1hi = hi;
        for (int it = 0; it < 32; ++it) {
            float mid = 0.5f * (l1lo + l1hi);
            if (sturmCount(alphas, betas, k, mid) >= k) l1hi = mid; else l1lo = mid;
        }
        float lam1 = 0.5f * (l1lo + l1hi);
        // lambda2 in [0, lam1]
        float l2lo = 0.0f, l2hi = lam1;
        for (int it = 0; it < 32; ++it) {
            float mid = 0.5f * (l2lo + l2hi);
            if (sturmCount(alphas, betas, k, mid) >= k - 1) l2hi = mid; else l2lo = mid;
        }
        float lam2 = 0.5f * (l2lo + l2hi);
        // Chebyshev interval top
        float bU = lam2 + 0.08f * (lam1 - lam2);
        bU = fminf(fmaxf(bU, 0.70f * lam1), 0.999f * lam1);
        red[33] = bU;
        // Inverse iteration for Ritz weights y
        float sigma = lam1 + fmaxf(2e-6f * fabsf(lam1), 1e-18f);
        float* cp = y2s;
        float* dp = y2s + 128;
        for (int i = 0; i < k; ++i) yv[i] = 1.0f;
        for (int r = 0; r < 2; ++r) {
            float m = alphas[0] - sigma;
            cp[0] = (k > 1) ? betas[0] / m : 0.0f;
            dp[0] = yv[0] / m;
            for (int i = 1; i < k; ++i) {
                float mi = alphas[i] - sigma - betas[i - 1] * cp[i - 1];
                cp[i] = (i < k - 1) ? betas[i] / mi : 0.0f;
                dp[i] = (yv[i] - betas[i - 1] * dp[i - 1]) / mi;
            }
            yv[k - 1] = dp[k - 1];
            for (int i = k - 2; i >= 0; --i) yv[i] = dp[i] - cp[i] * yv[i + 1];
            float nrm = 0.0f;
            for (int i = 0; i < k; ++i) nrm += yv[i] * yv[i];
            nrm = rsqrtf(fmaxf(nrm, 1e-30f));
            for (int i = 0; i < k; ++i) yv[i] *= nrm;
        }
    }
    __syncthreads();
    const float bU = red[33];
    __syncthreads();

    // ---- Ritz combination ----
    if (act) {
        float x = 0.0f;
        for (int j = 0; j < kEff; ++j)
            x = fmaf(yv[j], Vs[j * 256 + t], x);
        v[t] = x;
    }
    __syncthreads();
    {
        float n2 = blockSum(act ? v[t] * v[t] : 0.0f, red, t);
        if (act) v[t] *= rsqrtf(fmaxf(n2, 1e-30f));
    }
    __syncthreads();

    // ---- Chebyshev polish on [0, bU]; exit on residual (R8 criterion) ----
    const float inv2 = 2.0f / bU;
    for (int sweep = 0; sweep < 6; ++sweep) {
        float s = symMatvecB(blocks, v, y2s, t);
        float rho = blockSum(act ? v[t] * s : 0.0f, red, t);
        float d = act ? (s - rho * v[t]) : 0.0f;
        float r2 = blockSum(d * d, red, t);
        float tol = 4e-6f * rho;
        if (r2 < tol * tol) break;

        if (act) {
            vp[t] = v[t];
            v[t] = inv2 * s - v[t];
        }
        __syncthreads();
        for (int m = 0; m < 16; ++m) {
            float z = symMatvecB(blocks, v, y2s, t);
            if (act) {
                float vn = 2.0f * inv2 * z - 2.0f * v[t] - vp[t];
                vp[t] = v[t];
                v[t] = vn;
            }
            __syncthreads();
        }
        float n2 = blockSum(act ? v[t] * v[t] : 0.0f, red, t);
        if (act) v[t] *= rsqrtf(fmaxf(n2, 1e-30f));
        __syncthreads();
    }

    {
        float n2 = blockSum(act ? v[t] * v[t] : 0.0f, red, t);
        if (act) v[t] *= (1.0f / sqrtf(fmaxf(n2, 1e-30f)));
        __syncthreads();
    }

    // ---- Sign fix ----
    float av = act ? fabsf(v[t]) : -1.0f;
    float mx = blockMax(av, red, t);
    int idx = (act && av == mx) ? t : 1024;
    int imin = blockMinInt(idx, red, t);
    if (t == imin) red[41] = (v[t] < 0.0f) ? -1.0f : 1.0f;
    __syncthreads();
    if (act) out[b * 256 + t] = v[t] * red[41];
}

// ---------------------------------------------------------------------------
extern "C" void kernel_launch(void* const* d_in, const int* in_sizes, int n_in,
                              void* d_out, int out_size) {
    const float* x = (const float*)d_in[0];
    const float* w = (const float*)d_in[1];
    float* out = (float*)d_out;

    cudaFuncSetAttribute(k_eig, cudaFuncAttributeMaxDynamicSharedMemorySize,
                         EIG_SMEM_BYTES);

    k_u<<<NCAPS, 256>>>(x, w);
    k_syrk<<<dim3(10, BATCH), 64>>>();
    k_eig<<<BATCH, 512, EIG_SMEM_BYTES>>>(out);
}

// round 12
// speedup vs baseline: 1.0964x; 1.0964x over previous
#include <cuda_runtime.h>
#include <cuda_bf16.h>
#include <cstdint>
#include <math.h>

#define BATCH 64
#define NCAPS 2048
#define IDIM 16
#define DOUT 256

typedef unsigned int u32;
typedef unsigned long long u64;

__device__ float g_u[(size_t)BATCH * NCAPS * DOUT];   // 134 MB
__device__ float g_C[(size_t)BATCH * DOUT * DOUT];    // K-half 0 partial
__device__ float g_C2[(size_t)BATCH * DOUT * DOUT];   // K-half 1 partial

// ---------------------------------------------------------------------------
// Stage 1: u[b,c,o] = sum_i x[b,c,i] * w[c,i,o]
// ---------------------------------------------------------------------------
__global__ void k_u(const float* __restrict__ x, const float* __restrict__ w) {
    const int c = blockIdx.x;
    const int o = threadIdx.x;

    __shared__ __align__(16) float Xs[BATCH * IDIM];

    float W[IDIM];
#pragma unroll
    for (int i = 0; i < IDIM; ++i)
        W[i] = w[((size_t)c * IDIM + i) * DOUT + o];

    for (int l = o; l < BATCH * IDIM; l += 256) {
        int bb = l >> 4, ii = l & 15;
        Xs[l] = x[((size_t)bb * NCAPS + c) * IDIM + ii];
    }
    __syncthreads();

    for (int bb = 0; bb < BATCH; ++bb) {
        const float4 x0 = *(const float4*)&Xs[bb * IDIM + 0];
        const float4 x1 = *(const float4*)&Xs[bb * IDIM + 4];
        const float4 x2 = *(const float4*)&Xs[bb * IDIM + 8];
        const float4 x3 = *(const float4*)&Xs[bb * IDIM + 12];
        float a0 = x0.x * W[0], a1 = x0.y * W[1], a2 = x0.z * W[2], a3 = x0.w * W[3];
        a0 = fmaf(x1.x, W[4], a0);  a1 = fmaf(x1.y, W[5], a1);
        a2 = fmaf(x1.z, W[6], a2);  a3 = fmaf(x1.w, W[7], a3);
        a0 = fmaf(x2.x, W[8], a0);  a1 = fmaf(x2.y, W[9], a1);
        a2 = fmaf(x2.z, W[10], a2); a3 = fmaf(x2.w, W[11], a3);
        a0 = fmaf(x3.x, W[12], a0); a1 = fmaf(x3.y, W[13], a1);
        a2 = fmaf(x3.z, W[14], a2); a3 = fmaf(x3.w, W[15], a3);
        g_u[((size_t)bb * NCAPS + c) * DOUT + o] = (a0 + a1) + (a2 + a3);
    }
}

// ---------------------------------------------------------------------------
// Stage 2: lower-triangle tiles of C_b = U_b^T U_b (FFMA2, cp.async dbuf)
// Split-K: grid (10, 64, 2); z selects K-half and output buffer.
// ---------------------------------------------------------------------------
__device__ __forceinline__ void cp16(u32 saddr, const float* g) {
    asm volatile("cp.async.ca.shared.global [%0], [%1], 16;\n" :: "r"(saddr), "l"(g));
}
__device__ __forceinline__ u64 dupf(float f) {
    u64 r;
    asm("mov.b64 %0, {%1, %1};" : "=l"(r) : "f"(f));
    return r;
}
__device__ __forceinline__ void ffma2(u64& acc, u64 a, u64 b) {
    asm("fma.rn.f32x2 %0, %1, %2, %0;" : "+l"(acc) : "l"(a), "l"(b));
}

__device__ __forceinline__ void sy_load(u32 sA, u32 sB,
                                        const float* Ub, int kc, int buf,
                                        int dbase, int ebase, bool diag, int tid) {
#pragma unroll
    for (int q = 0; q < 4; ++q) {
        int idx = q * 64 + tid;
        int r = idx >> 4;
        int c4 = (idx & 15) << 2;
        const float* srow = Ub + (size_t)(kc + r) * DOUT;
        u32 so = (u32)((buf * 1024 + r * 64 + c4) * 4);
        cp16(sA + so, srow + dbase + c4);
        if (!diag) cp16(sB + so, srow + ebase + c4);
    }
}

#define KHALF 1024

__global__ __launch_bounds__(64, 6) void k_syrk() {
    const int p = blockIdx.x;
    const int b = blockIdx.y;
    const int kz = blockIdx.z;            // K-half

    int dt, et;
    if (p < 1)      { dt = 0; et = 0; }
    else if (p < 3) { dt = 1; et = p - 1; }
    else if (p < 6) { dt = 2; et = p - 3; }
    else            { dt = 3; et = p - 6; }
    const bool diag = (dt == et);

    const int tid = threadIdx.x;
    const int tx = tid & 7, ty = tid >> 3;

    __shared__ __align__(16) float As[2][16][64];
    __shared__ __align__(16) float Bs[2][16][64];

    const float* Ub = g_u + (size_t)b * NCAPS * DOUT + (size_t)kz * KHALF * DOUT;
    const int dbase = dt * 64, ebase = et * 64;

    u64 acc[4][8];
#pragma unroll
    for (int i = 0; i < 4; ++i)
#pragma unroll
        for (int j = 0; j < 8; ++j) acc[i][j] = 0ull;

    u32 sA = (u32)__cvta_generic_to_shared(&As[0][0][0]);
    u32 sB = (u32)__cvta_generic_to_shared(&Bs[0][0][0]);

    sy_load(sA, sB, Ub, 0, 0, dbase, ebase, diag, tid);
    asm volatile("cp.async.commit_group;\n");

    const int NCH = KHALF / 16;   // 64
    for (int chunk = 0; chunk < NCH; ++chunk) {
        const int buf = chunk & 1;
        if (chunk + 1 < NCH) {
            sy_load(sA, sB, Ub, (chunk + 1) * 16, buf ^ 1, dbase, ebase, diag, tid);
            asm volatile("cp.async.commit_group;\n");
            asm volatile("cp.async.wait_group 1;\n");
        } else {
            asm volatile("cp.async.wait_group 0;\n");
        }
        __syncthreads();

#pragma unroll
        for (int kk = 0; kk < 16; ++kk) {
            ulonglong2 a01 = *(const ulonglong2*)&As[buf][kk][ty * 8];
            ulonglong2 a23 = *(const ulonglong2*)&As[buf][kk][ty * 8 + 4];
            const float* bp = diag ? &As[buf][kk][tx * 8] : &Bs[buf][kk][tx * 8];
            float4 bl = *(const float4*)bp;
            float4 bh = *(const float4*)(bp + 4);
            u64 bd[8];
            bd[0] = dupf(bl.x); bd[1] = dupf(bl.y); bd[2] = dupf(bl.z); bd[3] = dupf(bl.w);
            bd[4] = dupf(bh.x); bd[5] = dupf(bh.y); bd[6] = dupf(bh.z); bd[7] = dupf(bh.w);
            u64 ap[4] = {a01.x, a01.y, a23.x, a23.y};
#pragma unroll
            for (int ip = 0; ip < 4; ++ip)
#pragma unroll
                for (int j = 0; j < 8; ++j)
                    ffma2(acc[ip][j], ap[ip], bd[j]);
        }
        __syncthreads();
    }

    float* Cb = (kz == 0 ? g_C : g_C2) + (size_t)b * DOUT * DOUT;
#pragma unroll
    for (int ip = 0; ip < 4; ++ip) {
        int d0 = dbase + ty * 8 + 2 * ip;
#pragma unroll
        for (int j = 0; j < 8; ++j) {
            float2 val = *(float2*)&acc[ip][j];
            int e = ebase + tx * 8 + j;
            Cb[d0 * DOUT + e] = val.x;
            Cb[(d0 + 1) * DOUT + e] = val.y;
        }
    }
}

// ---------------------------------------------------------------------------
// Stage 3: top eigenvector via Chebyshev (R8-proven). 512 threads, 36 swizzled
// 32x32 blocks, 64 conflict-free pass-units, adaptive interval, residual exit.
// ---------------------------------------------------------------------------
#define NBLK 36
#define BLK_FLOATS 1024
#define NW 16
#define Y2S_STRIDE 264
#define EIG_SMEM_FLOATS (NBLK * BLK_FLOATS + 2 * 256 + 64 + NW * Y2S_STRIDE)
#define EIG_SMEM_BYTES (EIG_SMEM_FLOATS * 4)

__device__ const unsigned char SB_R[NBLK] = {
    0, 1,1, 2,2,2, 3,3,3,3, 4,4,4,4,4, 5,5,5,5,5,5,
    6,6,6,6,6,6,6, 7,7,7,7,7,7,7,7 };
__device__ const unsigned char SB_C[NBLK] = {
    0, 0,1, 0,1,2, 0,1,2,3, 0,1,2,3,4, 0,1,2,3,4,5,
    0,1,2,3,4,5,6, 0,1,2,3,4,5,6,7 };

__device__ const unsigned char UNITS[64] = {
    0, 32, 36, 64, 68, 72, 96, 100, 104, 108, 128, 132, 136, 140, 144, 160,
    164, 168, 172, 176, 180, 192, 196, 200, 204, 208, 212, 216, 224, 228, 232, 236,
    240, 244, 248, 252,
    33, 65, 69, 97, 101, 105, 129, 133, 137, 141, 161, 165, 169, 173, 177, 193,
    197, 201, 205, 209, 213, 225, 229, 233, 237, 241, 245, 249 };

__device__ __forceinline__ int sw_off(int r, int c) {
    return r * 32 + ((((c >> 2) ^ (r & 7)) << 2) | (c & 3));
}

__device__ __forceinline__ float warpSum(float v) {
#pragma unroll
    for (int o = 16; o; o >>= 1) v += __shfl_xor_sync(0xffffffffu, v, o);
    return v;
}
__device__ float blockSum(float val, float* red, int t) {
    val = warpSum(val);
    if ((t & 31) == 0) red[t >> 5] = val;
    __syncthreads();
    if (t < 32) {
        float x = (t < NW) ? red[t] : 0.0f;
        x = warpSum(x);
        if (t == 0) red[32] = x;
    }
    __syncthreads();
    float r = red[32];
    __syncthreads();
    return r;
}
__device__ float blockMax(float val, float* red, int t) {
#pragma unroll
    for (int o = 16; o; o >>= 1) val = fmaxf(val, __shfl_xor_sync(0xffffffffu, val, o));
    if ((t & 31) == 0) red[t >> 5] = val;
    __syncthreads();
    if (t < 32) {
        float x = (t < NW) ? red[t] : -1.0f;
#pragma unroll
        for (int o = 16; o; o >>= 1) x = fmaxf(x, __shfl_xor_sync(0xffffffffu, x, o));
        if (t == 0) red[32] = x;
    }
    __syncthreads();
    float r = red[32];
    __syncthreads();
    return r;
}
__device__ int blockMinInt(int val, float* redf, int t) {
    int* red = (int*)redf;
#pragma unroll
    for (int o = 16; o; o >>= 1) val = min(val, __shfl_xor_sync(0xffffffffu, val, o));
    if ((t & 31) == 0) red[t >> 5] = val;
    __syncthreads();
    if (t < 32) {
        int x = (t < NW) ? red[t] : 0x7fffffff;
#pragma unroll
        for (int o = 16; o; o >>= 1) x = min(x, __shfl_xor_sync(0xffffffffu, x, o));
        if (t == 0) red[32] = x;
    }
    __syncthreads();
    int r = red[32];
    __syncthreads();
    return r;
}

// y[t] = (C v)[t] for t<256. One internal __syncthreads.
__device__ __forceinline__ float symMatvecB(const float* __restrict__ blocks,
                                            const float* __restrict__ v,
                                            float* __restrict__ y2s,
                                            int t) {
    const int l = t & 31, w = t >> 5;
    float* myp = y2s + w * Y2S_STRIDE;

#pragma unroll
    for (int k = 0; k < 8; ++k) myp[32 * k + l] = 0.0f;

#pragma unroll
    for (int q = 0; q < 4; ++q) {
        const int enc = UNITS[w + 16 * q];
        const int R = enc >> 5, C = (enc >> 2) & 7, type = enc & 1;
        const float* blk = blocks + (R * (R + 1) / 2 + C) * BLK_FLOATS;
        if (type == 0) {
            const float4* vq = (const float4*)(v + 32 * C);
            const float* bl = blk + l * 32;
            const int lx = l & 7;
            float a0 = 0.f, a1 = 0.f, a2 = 0.f, a3 = 0.f;
#pragma unroll
            for (int qq = 0; qq < 8; ++qq) {
                float4 a = *(const float4*)(bl + ((qq ^ lx) << 2));
                float4 vv = vq[qq];
                a0 = fmaf(a.x, vv.x, a0);
                a1 = fmaf(a.y, vv.y, a1);
                a2 = fmaf(a.z, vv.z, a2);
                a3 = fmaf(a.w, vv.w, a3);
            }
            myp[32 * R + l] += (a0 + a1) + (a2 + a3);
        } else {
            const int hi = l >> 2, lo = l & 3;
            const float* vb = v + 32 * R;
            float a0 = 0.f, a1 = 0.f, a2 = 0.f, a3 = 0.f;
#pragma unroll
            for (int rq = 0; rq < 8; ++rq) {
                float4 vv = *(const float4*)(vb + 4 * rq);
                const float* base = blk + rq * 128;
                a0 = fmaf(base[       (((hi ^ ((4 * rq)     & 7)) << 2) | lo)], vv.x, a0);
                a1 = fmaf(base[32  + (((hi ^ ((4 * rq + 1) & 7)) << 2) | lo)], vv.y, a1);
                a2 = fmaf(base[64  + (((hi ^ ((4 * rq + 2) & 7)) << 2) | lo)], vv.z, a2);
                a3 = fmaf(base[96  + (((hi ^ ((4 * rq + 3) & 7)) << 2) | lo)], vv.w, a3);
            }
            myp[32 * C + l] += (a0 + a1) + (a2 + a3);
        }
    }
    __syncthreads();

    float y = 0.f;
    if (t < 256) {
#pragma unroll
        for (int ww = 0; ww < NW; ++ww) y += y2s[ww * Y2S_STRIDE + t];
    }
    return y;
}

__global__ __launch_bounds__(512, 1) void k_eig(float* __restrict__ out) {
    extern __shared__ __align__(16) float sm[];
    float* blocks = sm;                          // 36 * 1024
    float* v   = sm + NBLK * BLK_FLOATS;         // 256
    float* vp  = v + 256;                        // 256
    float* red = vp + 256;                       // 64
    float* y2s = red + 64;                       // 16 * 264

    const int b = blockIdx.x;
    const int t = threadIdx.x;
    const bool act = (t < 256);
    const float* Cb  = g_C  + (size_t)b * DOUT * DOUT;
    const float* Cb2 = g_C2 + (size_t)b * DOUT * DOUT;

    // Load 36 blocks (sum of both K-half buffers); diag blocks mirrored.
    for (int s = 0; s < NBLK; ++s) {
        const int R = SB_R[s], C = SB_C[s];
        float* dst = blocks + s * BLK_FLOATS;
#pragma unroll
        for (int k = 0; k < 2; ++k) {
            int idx = k * 512 + t;
            int r = idx >> 5, c = idx & 31;
            int off;
            if (R > C || c <= r) off = (32 * R + r) * DOUT + 32 * C + c;
            else                 off = (32 * C + c) * DOUT + 32 * R + r;
            dst[sw_off(r, c)] = Cb[off] + Cb2[off];
        }
    }
    if (act) v[t] = Cb[t * DOUT] + Cb2[t * DOUT];   // column 0
    __syncthreads();

    {
        float n2 = blockSum(act ? v[t] * v[t] : 0.0f, red, t);
        if (act) v[t] *= rsqrtf(fmaxf(n2, 1e-30f));
    }
    __syncthreads();

    // Warm-up power iterations
    for (int it = 0; it < 6; ++it) {
        float s = symMatvecB(blocks, v, y2s, t);
        float n2 = blockSum(s * s, red, t);
        if (act) v[t] = s * rsqrtf(fmaxf(n2, 1e-30f));
        __syncthreads();
    }

    // Chebyshev iteration on interval [0, (1-eps)*rho]
    float eps = 0.008f;
    float r2prev = 1e30f;
    for (int outer = 0; outer < 48; ++outer) {
        float s = symMatvecB(blocks, v, y2s, t);
        float rho = blockSum(act ? v[t] * s : 0.0f, red, t);
        float d = act ? (s - rho * v[t]) : 0.0f;
        float r2 = blockSum(d * d, red, t);
        float tol = 4e-6f * rho;
        if (r2 < tol * tol) break;
        if (r2 > 0.3f * r2prev) eps = fmaxf(eps * 0.45f, 3e-4f);
        r2prev = r2;

        const float inv2 = 2.0f / (rho * (1.0f - eps));
        if (act) {
            vp[t] = v[t];
            v[t] = inv2 * s - v[t];
        }
        __syncthreads();
        for (int m = 0; m < 16; ++m) {
            float z = symMatvecB(blocks, v, y2s, t);
            if (act) {
                float vn = 2.0f * inv2 * z - 2.0f * v[t] - vp[t];
                vp[t] = v[t];
                v[t] = vn;
            }
            __syncthreads();
        }
        float n2 = blockSum(act ? v[t] * v[t] : 0.0f, red, t);
        if (act) v[t] *= rsqrtf(fmaxf(n2, 1e-30f));
        __syncthreads();
    }

    {
        float n2 = blockSum(act ? v[t] * v[t] : 0.0f, red, t);
        if (act) v[t] *= (1.0f / sqrtf(fmaxf(n2, 1e-30f)));
        __syncthreads();
    }

    float av = act ? fabsf(v[t]) : -1.0f;
    float mx = blockMax(av, red, t);
    int idx = (act && av == mx) ? t : 1024;
    int imin = blockMinInt(idx, red, t);
    if (t == imin) red[41] = (v[t] < 0.0f) ? -1.0f : 1.0f;
    __syncthreads();
    if (act) out[b * 256 + t] = v[t] * red[41];
}

// ---------------------------------------------------------------------------
extern "C" void kernel_launch(void* const* d_in, const int* in_sizes, int n_in,
                              void* d_out, int out_size) {
    const float* x = (const float*)d_in[0];
    const float* w = (const float*)d_in[1];
    float* out = (float*)d_out;

    cudaFuncSetAttribute(k_eig, cudaFuncAttributeMaxDynamicSharedMemorySize,
                         EIG_SMEM_BYTES);

    k_u<<<NCAPS, 256>>>(x, w);
    k_syrk<<<dim3(10, BATCH, 2), 64>>>();
    k_eig<<<BATCH, 512, EIG_SMEM_BYTES>>>(out);
}

// round 13
// speedup vs baseline: 1.3927x; 1.2702x over previous
#include <cuda_runtime.h>
#include <cuda_bf16.h>
#include <cstdint>
#include <math.h>

#define BATCH 64
#define NCAPS 2048
#define IDIM 16
#define DOUT 256

typedef unsigned int u32;
typedef unsigned long long u64;

__device__ __nv_bfloat16 g_hi[(size_t)BATCH * NCAPS * DOUT];  // 67 MB [b][c][o]
__device__ __nv_bfloat16 g_lo[(size_t)BATCH * NCAPS * DOUT];  // 67 MB [b][c][o]
__device__ float g_C[(size_t)BATCH * DOUT * DOUT];            // 16 MB

// ---------------------------------------------------------------------------
// Stage 1: u[b,c,o] = sum_i x[b,c,i] * w[c,i,o]  -> bf16 hi/lo split
// ---------------------------------------------------------------------------
__global__ void k_u(const float* __restrict__ x, const float* __restrict__ w) {
    const int c = blockIdx.x;
    const int o = threadIdx.x;

    __shared__ __align__(16) float Xs[BATCH * IDIM];

    float W[IDIM];
#pragma unroll
    for (int i = 0; i < IDIM; ++i)
        W[i] = w[((size_t)c * IDIM + i) * DOUT + o];

    for (int l = o; l < BATCH * IDIM; l += 256) {
        int bb = l >> 4, ii = l & 15;
        Xs[l] = x[((size_t)bb * NCAPS + c) * IDIM + ii];
    }
    __syncthreads();

    for (int bb = 0; bb < BATCH; ++bb) {
        const float4 x0 = *(const float4*)&Xs[bb * IDIM + 0];
        const float4 x1 = *(const float4*)&Xs[bb * IDIM + 4];
        const float4 x2 = *(const float4*)&Xs[bb * IDIM + 8];
        const float4 x3 = *(const float4*)&Xs[bb * IDIM + 12];
        float a0 = x0.x * W[0], a1 = x0.y * W[1], a2 = x0.z * W[2], a3 = x0.w * W[3];
        a0 = fmaf(x1.x, W[4], a0);  a1 = fmaf(x1.y, W[5], a1);
        a2 = fmaf(x1.z, W[6], a2);  a3 = fmaf(x1.w, W[7], a3);
        a0 = fmaf(x2.x, W[8], a0);  a1 = fmaf(x2.y, W[9], a1);
        a2 = fmaf(x2.z, W[10], a2); a3 = fmaf(x2.w, W[11], a3);
        a0 = fmaf(x3.x, W[12], a0); a1 = fmaf(x3.y, W[13], a1);
        a2 = fmaf(x3.z, W[14], a2); a3 = fmaf(x3.w, W[15], a3);
        float val = (a0 + a1) + (a2 + a3);
        __nv_bfloat16 hi = __float2bfloat16_rn(val);
        float lof = val - __bfloat162float(hi);
        __nv_bfloat16 lo = __float2bfloat16_rn(lof);
        size_t idx = ((size_t)bb * NCAPS + c) * DOUT + o;
        g_hi[idx] = hi;
        g_lo[idx] = lo;
    }
}

// ---------------------------------------------------------------------------
// Stage 2: C_b = U_b^T U_b via mma.sync bf16 2-way split (hh + hl + lh).
// 64x64 triangular tiles, grid (10, 64), block 128 (4 warps), Kc=32 dbuf.
// SMEM panels k-major: [panel][buf][k(32)][o(64) pitch 72 bf16].
// ---------------------------------------------------------------------------
__device__ __forceinline__ void cp16b(u32 saddr, const void* g) {
    asm volatile("cp.async.ca.shared.global [%0], [%1], 16;\n" :: "r"(saddr), "l"(g));
}

#define PANEL_B 9216u        // 2 bufs * 32 rows * 144 bytes
#define BUF_B   4608u        // 32 rows * 144 bytes
#define ROW_B   144u         // 72 bf16 pitch

__global__ __launch_bounds__(128) void k_syrk_mma() {
    const int p = blockIdx.x;
    const int b = blockIdx.y;

    int dt, et;
    if (p < 1)      { dt = 0; et = 0; }
    else if (p < 3) { dt = 1; et = p - 1; }
    else if (p < 6) { dt = 2; et = p - 3; }
    else            { dt = 3; et = p - 6; }

    const int tid = threadIdx.x;
    const int wid = tid >> 5, lane = tid & 31;
    const int dbase = dt * 64, ebase = et * 64;

    __shared__ __align__(16) char smem[4 * PANEL_B];   // 36864 B
    const u32 sbase = (u32)__cvta_generic_to_shared(smem);

    const __nv_bfloat16* bh = g_hi + (size_t)b * NCAPS * DOUT;
    const __nv_bfloat16* bl = g_lo + (size_t)b * NCAPS * DOUT;

    float acc[8][4];
#pragma unroll
    for (int j = 0; j < 8; ++j)
#pragma unroll
        for (int q = 0; q < 4; ++q) acc[j][q] = 0.0f;

    // per-lane ldmatrix source-row offsets (bytes, relative to panel+buf base)
    const int grp = lane >> 3, li = lane & 7;
    const int o0 = wid * 16;
    // A (m16k16, .trans): grp0 m0-7/k0-7, grp1 m8-15/k0-7, grp2 m0-7/k8-15, grp3 m8-15/k8-15
    const u32 aRel = (u32)((li + ((grp >> 1) & 1) * 8) * ROW_B + (o0 + (grp & 1) * 8) * 2);
    // B (k16n8 pairs, .trans): grp0 n0-7/k0-7, grp1 n0-7/k8-15, grp2 n8-15/k0-7, grp3 n8-15/k8-15
    const u32 bRel = (u32)((li + (grp & 1) * 8) * ROW_B + (((grp >> 1) & 1) * 8) * 2);

    // loader: one Kc=32 chunk into buffer `buf`
    auto load_chunk = [&](int buf, int kc) {
        const __nv_bfloat16* srcs[4] = { bh + dbase, bl + dbase, bh + ebase, bl + ebase };
#pragma unroll
        for (int pp = 0; pp < 4; ++pp) {
#pragma unroll
            for (int i = 0; i < 2; ++i) {
                int idx = i * 128 + tid;          // 0..255
                int row = idx >> 3, ch = idx & 7;
                u32 dst = sbase + pp * PANEL_B + (u32)buf * BUF_B + (u32)row * ROW_B + (u32)ch * 16u;
                cp16b(dst, srcs[pp] + (size_t)(kc + row) * DOUT + ch * 8);
            }
        }
    };

    load_chunk(0, 0);
    asm volatile("cp.async.commit_group;\n");

    const int NCH = NCAPS / 32;   // 64
    for (int chunk = 0; chunk < NCH; ++chunk) {
        const int buf = chunk & 1;
        if (chunk + 1 < NCH) {
            load_chunk(buf ^ 1, (chunk + 1) * 32);
            asm volatile("cp.async.commit_group;\n");
            asm volatile("cp.async.wait_group 1;\n");
        } else {
            asm volatile("cp.async.wait_group 0;\n");
        }
        __syncthreads();

#pragma unroll
        for (int ss = 0; ss < 2; ++ss) {
            const u32 kbyte = (u32)buf * BUF_B + (u32)ss * 16u * ROW_B;
            u32 a_h[4], a_l[4];
            asm volatile("ldmatrix.sync.aligned.m8n8.x4.trans.shared.b16 {%0,%1,%2,%3}, [%4];"
                : "=r"(a_h[0]), "=r"(a_h[1]), "=r"(a_h[2]), "=r"(a_h[3])
                : "r"(sbase + 0 * PANEL_B + kbyte + aRel));
            asm volatile("ldmatrix.sync.aligned.m8n8.x4.trans.shared.b16 {%0,%1,%2,%3}, [%4];"
                : "=r"(a_l[0]), "=r"(a_l[1]), "=r"(a_l[2]), "=r"(a_l[3])
                : "r"(sbase + 1 * PANEL_B + kbyte + aRel));

#pragma unroll
            for (int nb = 0; nb < 4; ++nb) {
                u32 bhf[4], blf[4];
                u32 bAddr = sbase + 2 * PANEL_B + kbyte + bRel + (u32)nb * 32u;
                asm volatile("ldmatrix.sync.aligned.m8n8.x4.trans.shared.b16 {%0,%1,%2,%3}, [%4];"
                    : "=r"(bhf[0]), "=r"(bhf[1]), "=r"(bhf[2]), "=r"(bhf[3])
                    : "r"(bAddr));
                asm volatile("ldmatrix.sync.aligned.m8n8.x4.trans.shared.b16 {%0,%1,%2,%3}, [%4];"
                    : "=r"(blf[0]), "=r"(blf[1]), "=r"(blf[2]), "=r"(blf[3])
                    : "r"(bAddr + PANEL_B));

#define MMA4(C, A, B0, B1)                                                      \
    asm volatile("mma.sync.aligned.m16n8k16.row.col.f32.bf16.bf16.f32 "         \
                 "{%0,%1,%2,%3},{%4,%5,%6,%7},{%8,%9},{%0,%1,%2,%3};"           \
                 : "+f"(C[0]), "+f"(C[1]), "+f"(C[2]), "+f"(C[3])               \
                 : "r"(A[0]), "r"(A[1]), "r"(A[2]), "r"(A[3]), "r"(B0), "r"(B1))

                MMA4(acc[2 * nb],     a_h, bhf[0], bhf[1]);
                MMA4(acc[2 * nb + 1], a_h, bhf[2], bhf[3]);
                MMA4(acc[2 * nb],     a_h, blf[0], blf[1]);
                MMA4(acc[2 * nb + 1], a_h, blf[2], blf[3]);
                MMA4(acc[2 * nb],     a_l, bhf[0], bhf[1]);
                MMA4(acc[2 * nb + 1], a_l, bhf[2], bhf[3]);
#undef MMA4
            }
        }
        __syncthreads();
    }

    // Epilogue: c-frag m16n8 -> (row = lane/4 (+8), col = 2*(lane%4) (+1))
    float* Cb = g_C + (size_t)b * DOUT * DOUT;
    const int r0 = dbase + wid * 16 + (lane >> 2);
    const int c0 = ebase + (lane & 3) * 2;
#pragma unroll
    for (int j = 0; j < 8; ++j) {
        int e = c0 + 8 * j;
        *(float2*)&Cb[(size_t)r0 * DOUT + e]       = make_float2(acc[j][0], acc[j][1]);
        *(float2*)&Cb[(size_t)(r0 + 8) * DOUT + e] = make_float2(acc[j][2], acc[j][3]);
    }
}

// ---------------------------------------------------------------------------
// Stage 3: top eigenvector via Chebyshev (R8-proven). 512 threads, 36 swizzled
// 32x32 blocks, 64 conflict-free pass-units, adaptive interval, residual exit.
// ---------------------------------------------------------------------------
#define NBLK 36
#define BLK_FLOATS 1024
#define NW 16
#define Y2S_STRIDE 264
#define EIG_SMEM_FLOATS (NBLK * BLK_FLOATS + 2 * 256 + 64 + NW * Y2S_STRIDE)
#define EIG_SMEM_BYTES (EIG_SMEM_FLOATS * 4)

__device__ const unsigned char SB_R[NBLK] = {
    0, 1,1, 2,2,2, 3,3,3,3, 4,4,4,4,4, 5,5,5,5,5,5,
    6,6,6,6,6,6,6, 7,7,7,7,7,7,7,7 };
__device__ const unsigned char SB_C[NBLK] = {
    0, 0,1, 0,1,2, 0,1,2,3, 0,1,2,3,4, 0,1,2,3,4,5,
    0,1,2,3,4,5,6, 0,1,2,3,4,5,6,7 };

__device__ const unsigned char UNITS[64] = {
    0, 32, 36, 64, 68, 72, 96, 100, 104, 108, 128, 132, 136, 140, 144, 160,
    164, 168, 172, 176, 180, 192, 196, 200, 204, 208, 212, 216, 224, 228, 232, 236,
    240, 244, 248, 252,
    33, 65, 69, 97, 101, 105, 129, 133, 137, 141, 161, 165, 169, 173, 177, 193,
    197, 201, 205, 209, 213, 225, 229, 233, 237, 241, 245, 249 };

__device__ __forceinline__ int sw_off(int r, int c) {
    return r * 32 + ((((c >> 2) ^ (r & 7)) << 2) | (c & 3));
}

__device__ __forceinline__ float warpSum(float v) {
#pragma unroll
    for (int o = 16; o; o >>= 1) v += __shfl_xor_sync(0xffffffffu, v, o);
    return v;
}
__device__ float blockSum(float val, float* red, int t) {
    val = warpSum(val);
    if ((t & 31) == 0) red[t >> 5] = val;
    __syncthreads();
    if (t < 32) {
        float x = (t < NW) ? red[t] : 0.0f;
        x = warpSum(x);
        if (t == 0) red[32] = x;
    }
    __syncthreads();
    float r = red[32];
    __syncthreads();
    return r;
}
__device__ float blockMax(float val, float* red, int t) {
#pragma unroll
    for (int o = 16; o; o >>= 1) val = fmaxf(val, __shfl_xor_sync(0xffffffffu, val, o));
    if ((t & 31) == 0) red[t >> 5] = val;
    __syncthreads();
    if (t < 32) {
        float x = (t < NW) ? red[t] : -1.0f;
#pragma unroll
        for (int o = 16; o; o >>= 1) x = fmaxf(x, __shfl_xor_sync(0xffffffffu, x, o));
        if (t == 0) red[32] = x;
    }
    __syncthreads();
    float r = red[32];
    __syncthreads();
    return r;
}
__device__ int blockMinInt(int val, float* redf, int t) {
    int* red = (int*)redf;
#pragma unroll
    for (int o = 16; o; o >>= 1) val = min(val, __shfl_xor_sync(0xffffffffu, val, o));
    if ((t & 31) == 0) red[t >> 5] = val;
    __syncthreads();
    if (t < 32) {
        int x = (t < NW) ? red[t] : 0x7fffffff;
#pragma unroll
        for (int o = 16; o; o >>= 1) x = min(x, __shfl_xor_sync(0xffffffffu, x, o));
        if (t == 0) red[32] = x;
    }
    __syncthreads();
    int r = red[32];
    __syncthreads();
    return r;
}

__device__ __forceinline__ float symMatvecB(const float* __restrict__ blocks,
                                            const float* __restrict__ v,
                                            float* __restrict__ y2s,
                                            int t) {
    const int l = t & 31, w = t >> 5;
    float* myp = y2s + w * Y2S_STRIDE;

#pragma unroll
    for (int k = 0; k < 8; ++k) myp[32 * k + l] = 0.0f;

#pragma unroll
    for (int q = 0; q < 4; ++q) {
        const int enc = UNITS[w + 16 * q];
        const int R = enc >> 5, C = (enc >> 2) & 7, type = enc & 1;
        const float* blk = blocks + (R * (R + 1) / 2 + C) * BLK_FLOATS;
        if (type == 0) {
            const float4* vq = (const float4*)(v + 32 * C);
            const float* bl = blk + l * 32;
            const int lx = l & 7;
            float a0 = 0.f, a1 = 0.f, a2 = 0.f, a3 = 0.f;
#pragma unroll
            for (int qq = 0; qq < 8; ++qq) {
                float4 a = *(const float4*)(bl + ((qq ^ lx) << 2));
                float4 vv = vq[qq];
                a0 = fmaf(a.x, vv.x, a0);
                a1 = fmaf(a.y, vv.y, a1);
                a2 = fmaf(a.z, vv.z, a2);
                a3 = fmaf(a.w, vv.w, a3);
            }
            myp[32 * R + l] += (a0 + a1) + (a2 + a3);
        } else {
            const int hi = l >> 2, lo = l & 3;
            const float* vb = v + 32 * R;
            float a0 = 0.f, a1 = 0.f, a2 = 0.f, a3 = 0.f;
#pragma unroll
            for (int rq = 0; rq < 8; ++rq) {
                float4 vv = *(const float4*)(vb + 4 * rq);
                const float* base = blk + rq * 128;
                a0 = fmaf(base[       (((hi ^ ((4 * rq)     & 7)) << 2) | lo)], vv.x, a0);
                a1 = fmaf(base[32  + (((hi ^ ((4 * rq + 1) & 7)) << 2) | lo)], vv.y, a1);
                a2 = fmaf(base[64  + (((hi ^ ((4 * rq + 2) & 7)) << 2) | lo)], vv.z, a2);
                a3 = fmaf(base[96  + (((hi ^ ((4 * rq + 3) & 7)) << 2) | lo)], vv.w, a3);
            }
            myp[32 * C + l] += (a0 + a1) + (a2 + a3);
        }
    }
    __syncthreads();

    float y = 0.f;
    if (t < 256) {
#pragma unroll
        for (int ww = 0; ww < NW; ++ww) y += y2s[ww * Y2S_STRIDE + t];
    }
    return y;
}

__global__ __launch_bounds__(512, 1) void k_eig(float* __restrict__ out) {
    extern __shared__ __align__(16) float sm[];
    float* blocks = sm;                          // 36 * 1024
    float* v   = sm + NBLK * BLK_FLOATS;         // 256
    float* vp  = v + 256;                        // 256
    float* red = vp + 256;                       // 64
    float* y2s = red + 64;                       // 16 * 264

    const int b = blockIdx.x;
    const int t = threadIdx.x;
    const bool act = (t < 256);
    const float* Cb = g_C + (size_t)b * DOUT * DOUT;

    for (int s = 0; s < NBLK; ++s) {
        const int R = SB_R[s], C = SB_C[s];
        float* dst = blocks + s * BLK_FLOATS;
#pragma unroll
        for (int k = 0; k < 2; ++k) {
            int idx = k * 512 + t;
            int r = idx >> 5, c = idx & 31;
            float val;
            if (R > C || c <= r) val = Cb[(32 * R + r) * DOUT + 32 * C + c];
            else                 val = Cb[(32 * C + c) * DOUT + 32 * R + r];
            dst[sw_off(r, c)] = val;
        }
    }
    if (act) v[t] = Cb[t * DOUT];
    __syncthreads();

    {
        float n2 = blockSum(act ? v[t] * v[t] : 0.0f, red, t);
        if (act) v[t] *= rsqrtf(fmaxf(n2, 1e-30f));
    }
    __syncthreads();

    for (int it = 0; it < 6; ++it) {
        float s = symMatvecB(blocks, v, y2s, t);
        float n2 = blockSum(s * s, red, t);
        if (act) v[t] = s * rsqrtf(fmaxf(n2, 1e-30f));
        __syncthreads();
    }

    float eps = 0.008f;
    float r2prev = 1e30f;
    for (int outer = 0; outer < 48; ++outer) {
        float s = symMatvecB(blocks, v, y2s, t);
        float rho = blockSum(act ? v[t] * s : 0.0f, red, t);
        float d = act ? (s - rho * v[t]) : 0.0f;
        float r2 = blockSum(d * d, red, t);
        float tol = 4e-6f * rho;
        if (r2 < tol * tol) break;
        if (r2 > 0.3f * r2prev) eps = fmaxf(eps * 0.45f, 3e-4f);
        r2prev = r2;

        const float inv2 = 2.0f / (rho * (1.0f - eps));
        if (act) {
            vp[t] = v[t];
            v[t] = inv2 * s - v[t];
        }
        __syncthreads();
        for (int m = 0; m < 16; ++m) {
            float z = symMatvecB(blocks, v, y2s, t);
            if (act) {
                float vn = 2.0f * inv2 * z - 2.0f * v[t] - vp[t];
                vp[t] = v[t];
                v[t] = vn;
            }
            __syncthreads();
        }
        float n2 = blockSum(act ? v[t] * v[t] : 0.0f, red, t);
        if (act) v[t] *= rsqrtf(fmaxf(n2, 1e-30f));
        __syncthreads();
    }

    {
        float n2 = blockSum(act ? v[t] * v[t] : 0.0f, red, t);
        if (act) v[t] *= (1.0f / sqrtf(fmaxf(n2, 1e-30f)));
        __syncthreads();
    }

    float av = act ? fabsf(v[t]) : -1.0f;
    float mx = blockMax(av, red, t);
    int idx = (act && av == mx) ? t : 1024;
    int imin = blockMinInt(idx, red, t);
    if (t == imin) red[41] = (v[t] < 0.0f) ? -1.0f : 1.0f;
    __syncthreads();
    if (act) out[b * 256 + t] = v[t] * red[41];
}

// ---------------------------------------------------------------------------
extern "C" void kernel_launch(void* const* d_in, const int* in_sizes, int n_in,
                              void* d_out, int out_size) {
    const float* x = (const float*)d_in[0];
    const float* w = (const float*)d_in[1];
    float* out = (float*)d_out;

    cudaFuncSetAttribute(k_eig, cudaFuncAttributeMaxDynamicSharedMemorySize,
                         EIG_SMEM_BYTES);

    k_u<<<NCAPS, 256>>>(x, w);
    k_syrk_mma<<<dim3(10, BATCH), 128>>>();
    k_eig<<<BATCH, 512, EIG_SMEM_BYTES>>>(out);
}

// round 14
// speedup vs baseline: 1.5074x; 1.0824x over previous
#include <cuda_runtime.h>
#include <cuda_bf16.h>
#include <cstdint>
#include <math.h>

#define BATCH 64
#define NCAPS 2048
#define IDIM 16
#define DOUT 256

typedef unsigned int u32;
typedef unsigned long long u64;

__device__ __nv_bfloat16 g_hi[(size_t)BATCH * NCAPS * DOUT];  // 67 MB [b][c][o]
__device__ __nv_bfloat16 g_lo[(size_t)BATCH * NCAPS * DOUT];  // 67 MB [b][c][o]
__device__ float g_C[(size_t)BATCH * DOUT * DOUT];            // 16 MB

// ---------------------------------------------------------------------------
// Stage 1: u[b,c,o] = sum_i x[b,c,i] * w[c,i,o]  -> bf16 hi/lo split
// ---------------------------------------------------------------------------
__global__ void k_u(const float* __restrict__ x, const float* __restrict__ w) {
    const int c = blockIdx.x;
    const int o = threadIdx.x;

    __shared__ __align__(16) float Xs[BATCH * IDIM];

    float W[IDIM];
#pragma unroll
    for (int i = 0; i < IDIM; ++i)
        W[i] = w[((size_t)c * IDIM + i) * DOUT + o];

    for (int l = o; l < BATCH * IDIM; l += 256) {
        int bb = l >> 4, ii = l & 15;
        Xs[l] = x[((size_t)bb * NCAPS + c) * IDIM + ii];
    }
    __syncthreads();

    for (int bb = 0; bb < BATCH; ++bb) {
        const float4 x0 = *(const float4*)&Xs[bb * IDIM + 0];
        const float4 x1 = *(const float4*)&Xs[bb * IDIM + 4];
        const float4 x2 = *(const float4*)&Xs[bb * IDIM + 8];
        const float4 x3 = *(const float4*)&Xs[bb * IDIM + 12];
        float a0 = x0.x * W[0], a1 = x0.y * W[1], a2 = x0.z * W[2], a3 = x0.w * W[3];
        a0 = fmaf(x1.x, W[4], a0);  a1 = fmaf(x1.y, W[5], a1);
        a2 = fmaf(x1.z, W[6], a2);  a3 = fmaf(x1.w, W[7], a3);
        a0 = fmaf(x2.x, W[8], a0);  a1 = fmaf(x2.y, W[9], a1);
        a2 = fmaf(x2.z, W[10], a2); a3 = fmaf(x2.w, W[11], a3);
        a0 = fmaf(x3.x, W[12], a0); a1 = fmaf(x3.y, W[13], a1);
        a2 = fmaf(x3.z, W[14], a2); a3 = fmaf(x3.w, W[15], a3);
        float val = (a0 + a1) + (a2 + a3);
        __nv_bfloat16 hi = __float2bfloat16_rn(val);
        float lof = val - __bfloat162float(hi);
        __nv_bfloat16 lo = __float2bfloat16_rn(lof);
        size_t idx = ((size_t)bb * NCAPS + c) * DOUT + o;
        g_hi[idx] = hi;
        g_lo[idx] = lo;
    }
}

// ---------------------------------------------------------------------------
// Stage 2: C_b = U_b^T U_b via mma.sync bf16 2-way split (hh + hl + lh).
// 64x64 triangular tiles, grid (10, 64), block 128 (4 warps), Kc=32 dbuf.
// ---------------------------------------------------------------------------
__device__ __forceinline__ void cp16b(u32 saddr, const void* g) {
    asm volatile("cp.async.ca.shared.global [%0], [%1], 16;\n" :: "r"(saddr), "l"(g));
}

#define PANEL_B 9216u        // 2 bufs * 32 rows * 144 bytes
#define BUF_B   4608u        // 32 rows * 144 bytes
#define ROW_B   144u         // 72 bf16 pitch

__global__ __launch_bounds__(128) void k_syrk_mma() {
    const int p = blockIdx.x;
    const int b = blockIdx.y;

    int dt, et;
    if (p < 1)      { dt = 0; et = 0; }
    else if (p < 3) { dt = 1; et = p - 1; }
    else if (p < 6) { dt = 2; et = p - 3; }
    else            { dt = 3; et = p - 6; }

    const int tid = threadIdx.x;
    const int wid = tid >> 5, lane = tid & 31;
    const int dbase = dt * 64, ebase = et * 64;

    __shared__ __align__(16) char smem[4 * PANEL_B];   // 36864 B
    const u32 sbase = (u32)__cvta_generic_to_shared(smem);

    const __nv_bfloat16* bh = g_hi + (size_t)b * NCAPS * DOUT;
    const __nv_bfloat16* bl = g_lo + (size_t)b * NCAPS * DOUT;

    float acc[8][4];
#pragma unroll
    for (int j = 0; j < 8; ++j)
#pragma unroll
        for (int q = 0; q < 4; ++q) acc[j][q] = 0.0f;

    const int grp = lane >> 3, li = lane & 7;
    const int o0 = wid * 16;
    const u32 aRel = (u32)((li + ((grp >> 1) & 1) * 8) * ROW_B + (o0 + (grp & 1) * 8) * 2);
    const u32 bRel = (u32)((li + (grp & 1) * 8) * ROW_B + (((grp >> 1) & 1) * 8) * 2);

    auto load_chunk = [&](int buf, int kc) {
        const __nv_bfloat16* srcs[4] = { bh + dbase, bl + dbase, bh + ebase, bl + ebase };
#pragma unroll
        for (int pp = 0; pp < 4; ++pp) {
#pragma unroll
            for (int i = 0; i < 2; ++i) {
                int idx = i * 128 + tid;
                int row = idx >> 3, ch = idx & 7;
                u32 dst = sbase + pp * PANEL_B + (u32)buf * BUF_B + (u32)row * ROW_B + (u32)ch * 16u;
                cp16b(dst, srcs[pp] + (size_t)(kc + row) * DOUT + ch * 8);
            }
        }
    };

    load_chunk(0, 0);
    asm volatile("cp.async.commit_group;\n");

    const int NCH = NCAPS / 32;   // 64
    for (int chunk = 0; chunk < NCH; ++chunk) {
        const int buf = chunk & 1;
        if (chunk + 1 < NCH) {
            load_chunk(buf ^ 1, (chunk + 1) * 32);
            asm volatile("cp.async.commit_group;\n");
            asm volatile("cp.async.wait_group 1;\n");
        } else {
            asm volatile("cp.async.wait_group 0;\n");
        }
        __syncthreads();

#pragma unroll
        for (int ss = 0; ss < 2; ++ss) {
            const u32 kbyte = (u32)buf * BUF_B + (u32)ss * 16u * ROW_B;
            u32 a_h[4], a_l[4];
            asm volatile("ldmatrix.sync.aligned.m8n8.x4.trans.shared.b16 {%0,%1,%2,%3}, [%4];"
                : "=r"(a_h[0]), "=r"(a_h[1]), "=r"(a_h[2]), "=r"(a_h[3])
                : "r"(sbase + 0 * PANEL_B + kbyte + aRel));
            asm volatile("ldmatrix.sync.aligned.m8n8.x4.trans.shared.b16 {%0,%1,%2,%3}, [%4];"
                : "=r"(a_l[0]), "=r"(a_l[1]), "=r"(a_l[2]), "=r"(a_l[3])
                : "r"(sbase + 1 * PANEL_B + kbyte + aRel));

#pragma unroll
            for (int nb = 0; nb < 4; ++nb) {
                u32 bhf[4], blf[4];
                u32 bAddr = sbase + 2 * PANEL_B + kbyte + bRel + (u32)nb * 32u;
                asm volatile("ldmatrix.sync.aligned.m8n8.x4.trans.shared.b16 {%0,%1,%2,%3}, [%4];"
                    : "=r"(bhf[0]), "=r"(bhf[1]), "=r"(bhf[2]), "=r"(bhf[3])
                    : "r"(bAddr));
                asm volatile("ldmatrix.sync.aligned.m8n8.x4.trans.shared.b16 {%0,%1,%2,%3}, [%4];"
                    : "=r"(blf[0]), "=r"(blf[1]), "=r"(blf[2]), "=r"(blf[3])
                    : "r"(bAddr + PANEL_B));

#define MMA4(C, A, B0, B1)                                                      \
    asm volatile("mma.sync.aligned.m16n8k16.row.col.f32.bf16.bf16.f32 "         \
                 "{%0,%1,%2,%3},{%4,%5,%6,%7},{%8,%9},{%0,%1,%2,%3};"           \
                 : "+f"(C[0]), "+f"(C[1]), "+f"(C[2]), "+f"(C[3])               \
                 : "r"(A[0]), "r"(A[1]), "r"(A[2]), "r"(A[3]), "r"(B0), "r"(B1))

                MMA4(acc[2 * nb],     a_h, bhf[0], bhf[1]);
                MMA4(acc[2 * nb + 1], a_h, bhf[2], bhf[3]);
                MMA4(acc[2 * nb],     a_h, blf[0], blf[1]);
                MMA4(acc[2 * nb + 1], a_h, blf[2], blf[3]);
                MMA4(acc[2 * nb],     a_l, bhf[0], bhf[1]);
                MMA4(acc[2 * nb + 1], a_l, bhf[2], bhf[3]);
#undef MMA4
            }
        }
        __syncthreads();
    }

    float* Cb = g_C + (size_t)b * DOUT * DOUT;
    const int r0 = dbase + wid * 16 + (lane >> 2);
    const int c0 = ebase + (lane & 3) * 2;
#pragma unroll
    for (int j = 0; j < 8; ++j) {
        int e = c0 + 8 * j;
        *(float2*)&Cb[(size_t)r0 * DOUT + e]       = make_float2(acc[j][0], acc[j][1]);
        *(float2*)&Cb[(size_t)(r0 + 8) * DOUT + e] = make_float2(acc[j][2], acc[j][3]);
    }
}

// ---------------------------------------------------------------------------
// Stage 3: top eigenvector via Chebyshev. 512 threads, 36 swizzled 32x32
// blocks, 64 conflict-free pass-units. Trimmed schedule: 3 warmups,
// eps0=0.012 decay 0.5, tol 8e-6.
// ---------------------------------------------------------------------------
#define NBLK 36
#define BLK_FLOATS 1024
#define NW 16
#define Y2S_STRIDE 264
#define EIG_SMEM_FLOATS (NBLK * BLK_FLOATS + 2 * 256 + 64 + NW * Y2S_STRIDE)
#define EIG_SMEM_BYTES (EIG_SMEM_FLOATS * 4)

__device__ const unsigned char SB_R[NBLK] = {
    0, 1,1, 2,2,2, 3,3,3,3, 4,4,4,4,4, 5,5,5,5,5,5,
    6,6,6,6,6,6,6, 7,7,7,7,7,7,7,7 };
__device__ const unsigned char SB_C[NBLK] = {
    0, 0,1, 0,1,2, 0,1,2,3, 0,1,2,3,4, 0,1,2,3,4,5,
    0,1,2,3,4,5,6, 0,1,2,3,4,5,6,7 };

__device__ const unsigned char UNITS[64] = {
    0, 32, 36, 64, 68, 72, 96, 100, 104, 108, 128, 132, 136, 140, 144, 160,
    164, 168, 172, 176, 180, 192, 196, 200, 204, 208, 212, 216, 224, 228, 232, 236,
    240, 244, 248, 252,
    33, 65, 69, 97, 101, 105, 129, 133, 137, 141, 161, 165, 169, 173, 177, 193,
    197, 201, 205, 209, 213, 225, 229, 233, 237, 241, 245, 249 };

__device__ __forceinline__ int sw_off(int r, int c) {
    return r * 32 + ((((c >> 2) ^ (r & 7)) << 2) | (c & 3));
}

__device__ __forceinline__ float warpSum(float v) {
#pragma unroll
    for (int o = 16; o; o >>= 1) v += __shfl_xor_sync(0xffffffffu, v, o);
    return v;
}
__device__ float blockSum(float val, float* red, int t) {
    val = warpSum(val);
    if ((t & 31) == 0) red[t >> 5] = val;
    __syncthreads();
    if (t < 32) {
        float x = (t < NW) ? red[t] : 0.0f;
        x = warpSum(x);
        if (t == 0) red[32] = x;
    }
    __syncthreads();
    float r = red[32];
    __syncthreads();
    return r;
}
__device__ float blockMax(float val, float* red, int t) {
#pragma unroll
    for (int o = 16; o; o >>= 1) val = fmaxf(val, __shfl_xor_sync(0xffffffffu, val, o));
    if ((t & 31) == 0) red[t >> 5] = val;
    __syncthreads();
    if (t < 32) {
        float x = (t < NW) ? red[t] : -1.0f;
#pragma unroll
        for (int o = 16; o; o >>= 1) x = fmaxf(x, __shfl_xor_sync(0xffffffffu, x, o));
        if (t == 0) red[32] = x;
    }
    __syncthreads();
    float r = red[32];
    __syncthreads();
    return r;
}
__device__ int blockMinInt(int val, float* redf, int t) {
    int* red = (int*)redf;
#pragma unroll
    for (int o = 16; o; o >>= 1) val = min(val, __shfl_xor_sync(0xffffffffu, val, o));
    if ((t & 31) == 0) red[t >> 5] = val;
    __syncthreads();
    if (t < 32) {
        int x = (t < NW) ? red[t] : 0x7fffffff;
#pragma unroll
        for (int o = 16; o; o >>= 1) x = min(x, __shfl_xor_sync(0xffffffffu, x, o));
        if (t == 0) red[32] = x;
    }
    __syncthreads();
    int r = red[32];
    __syncthreads();
    return r;
}

__device__ __forceinline__ float symMatvecB(const float* __restrict__ blocks,
                                            const float* __restrict__ v,
                                            float* __restrict__ y2s,
                                            int t) {
    const int l = t & 31, w = t >> 5;
    float* myp = y2s + w * Y2S_STRIDE;

#pragma unroll
    for (int k = 0; k < 8; ++k) myp[32 * k + l] = 0.0f;

#pragma unroll
    for (int q = 0; q < 4; ++q) {
        const int enc = UNITS[w + 16 * q];
        const int R = enc >> 5, C = (enc >> 2) & 7, type = enc & 1;
        const float* blk = blocks + (R * (R + 1) / 2 + C) * BLK_FLOATS;
        if (type == 0) {
            const float4* vq = (const float4*)(v + 32 * C);
            const float* bl = blk + l * 32;
            const int lx = l & 7;
            float a0 = 0.f, a1 = 0.f, a2 = 0.f, a3 = 0.f;
#pragma unroll
            for (int qq = 0; qq < 8; ++qq) {
                float4 a = *(const float4*)(bl + ((qq ^ lx) << 2));
                float4 vv = vq[qq];
                a0 = fmaf(a.x, vv.x, a0);
                a1 = fmaf(a.y, vv.y, a1);
                a2 = fmaf(a.z, vv.z, a2);
                a3 = fmaf(a.w, vv.w, a3);
            }
            myp[32 * R + l] += (a0 + a1) + (a2 + a3);
        } else {
            const int hi = l >> 2, lo = l & 3;
            const float* vb = v + 32 * R;
            float a0 = 0.f, a1 = 0.f, a2 = 0.f, a3 = 0.f;
#pragma unroll
            for (int rq = 0; rq < 8; ++rq) {
                float4 vv = *(const float4*)(vb + 4 * rq);
                const float* base = blk + rq * 128;
                a0 = fmaf(base[       (((hi ^ ((4 * rq)     & 7)) << 2) | lo)], vv.x, a0);
                a1 = fmaf(base[32  + (((hi ^ ((4 * rq + 1) & 7)) << 2) | lo)], vv.y, a1);
                a2 = fmaf(base[64  + (((hi ^ ((4 * rq + 2) & 7)) << 2) | lo)], vv.z, a2);
                a3 = fmaf(base[96  + (((hi ^ ((4 * rq + 3) & 7)) << 2) | lo)], vv.w, a3);
            }
            myp[32 * C + l] += (a0 + a1) + (a2 + a3);
        }
    }
    __syncthreads();

    float y = 0.f;
    if (t < 256) {
#pragma unroll
        for (int ww = 0; ww < NW; ++ww) y += y2s[ww * Y2S_STRIDE + t];
    }
    return y;
}

__global__ __launch_bounds__(512, 1) void k_eig(float* __restrict__ out) {
    extern __shared__ __align__(16) float sm[];
    float* blocks = sm;                          // 36 * 1024
    float* v   = sm + NBLK * BLK_FLOATS;         // 256
    float* vp  = v + 256;                        // 256
    float* red = vp + 256;                       // 64
    float* y2s = red + 64;                       // 16 * 264

    const int b = blockIdx.x;
    const int t = threadIdx.x;
    const bool act = (t < 256);
    const float* Cb = g_C + (size_t)b * DOUT * DOUT;

    for (int s = 0; s < NBLK; ++s) {
        const int R = SB_R[s], C = SB_C[s];
        float* dst = blocks + s * BLK_FLOATS;
#pragma unroll
        for (int k = 0; k < 2; ++k) {
            int idx = k * 512 + t;
            int r = idx >> 5, c = idx & 31;
            float val;
            if (R > C || c <= r) val = Cb[(32 * R + r) * DOUT + 32 * C + c];
            else                 val = Cb[(32 * C + c) * DOUT + 32 * R + r];
            dst[sw_off(r, c)] = val;
        }
    }
    if (act) v[t] = Cb[t * DOUT];
    __syncthreads();

    {
        float n2 = blockSum(act ? v[t] * v[t] : 0.0f, red, t);
        if (act) v[t] *= rsqrtf(fmaxf(n2, 1e-30f));
    }
    __syncthreads();

    // Warm-up power iterations (seed rho)
    for (int it = 0; it < 3; ++it) {
        float s = symMatvecB(blocks, v, y2s, t);
        float n2 = blockSum(s * s, red, t);
        if (act) v[t] = s * rsqrtf(fmaxf(n2, 1e-30f));
        __syncthreads();
    }

    // Chebyshev on [0, (1-eps)*rho], residual exit
    float eps = 0.012f;
    float r2prev = 1e30f;
    for (int outer = 0; outer < 48; ++outer) {
        float s = symMatvecB(blocks, v, y2s, t);
        float rho = blockSum(act ? v[t] * s : 0.0f, red, t);
        float d = act ? (s - rho * v[t]) : 0.0f;
        float r2 = blockSum(d * d, red, t);
        float tol = 8e-6f * rho;
        if (r2 < tol * tol) break;
        if (r2 > 0.3f * r2prev) eps = fmaxf(eps * 0.5f, 1e-3f);
        r2prev = r2;

        const float inv2 = 2.0f / (rho * (1.0f - eps));
        if (act) {
            vp[t] = v[t];
            v[t] = inv2 * s - v[t];
        }
        __syncthreads();
        for (int m = 0; m < 16; ++m) {
            float z = symMatvecB(blocks, v, y2s, t);
            if (act) {
                float vn = 2.0f * inv2 * z - 2.0f * v[t] - vp[t];
                vp[t] = v[t];
                v[t] = vn;
            }
            __syncthreads();
        }
        float n2 = blockSum(act ? v[t] * v[t] : 0.0f, red, t);
        if (act) v[t] *= rsqrtf(fmaxf(n2, 1e-30f));
        __syncthreads();
    }

    {
        float n2 = blockSum(act ? v[t] * v[t] : 0.0f, red, t);
        if (act) v[t] *= (1.0f / sqrtf(fmaxf(n2, 1e-30f)));
        __syncthreads();
    }

    float av = act ? fabsf(v[t]) : -1.0f;
    float mx = blockMax(av, red, t);
    int idx = (act && av == mx) ? t : 1024;
    int imin = blockMinInt(idx, red, t);
    if (t == imin) red[41] = (v[t] < 0.0f) ? -1.0f : 1.0f;
    __syncthreads();
    if (act) out[b * 256 + t] = v[t] * red[41];
}

// ---------------------------------------------------------------------------
extern "C" void kernel_launch(void* const* d_in, const int* in_sizes, int n_in,
                              void* d_out, int out_size) {
    const float* x = (const float*)d_in[0];
    const float* w = (const float*)d_in[1];
    float* out = (float*)d_out;

    cudaFuncSetAttribute(k_eig, cudaFuncAttributeMaxDynamicSharedMemorySize,
                         EIG_SMEM_BYTES);

    k_u<<<NCAPS, 256>>>(x, w);
    k_syrk_mma<<<dim3(10, BATCH), 128>>>();
    k_eig<<<BATCH, 512, EIG_SMEM_BYTES>>>(out);
}

// round 15
// speedup vs baseline: 1.6241x; 1.0774x over previous
#include <cuda_runtime.h>
#include <cuda_bf16.h>
#include <cstdint>
#include <math.h>

#define BATCH 64
#define NCAPS 2048
#define IDIM 16
#define DOUT 256

typedef unsigned int u32;
typedef unsigned long long u64;

__device__ __nv_bfloat16 g_hi[(size_t)BATCH * NCAPS * DOUT];  // 67 MB [b][c][o]
__device__ __nv_bfloat16 g_lo[(size_t)BATCH * NCAPS * DOUT];  // 67 MB [b][c][o]
__device__ float g_C[(size_t)BATCH * DOUT * DOUT];            // 16 MB

// ---------------------------------------------------------------------------
// Stage 1: u[b,c,o] = sum_i x[b,c,i] * w[c,i,o]  -> bf16 hi/lo split
// ---------------------------------------------------------------------------
__global__ void k_u(const float* __restrict__ x, const float* __restrict__ w) {
    const int c = blockIdx.x;
    const int o = threadIdx.x;

    __shared__ __align__(16) float Xs[BATCH * IDIM];

    float W[IDIM];
#pragma unroll
    for (int i = 0; i < IDIM; ++i)
        W[i] = w[((size_t)c * IDIM + i) * DOUT + o];

    for (int l = o; l < BATCH * IDIM; l += 256) {
        int bb = l >> 4, ii = l & 15;
        Xs[l] = x[((size_t)bb * NCAPS + c) * IDIM + ii];
    }
    __syncthreads();

    for (int bb = 0; bb < BATCH; ++bb) {
        const float4 x0 = *(const float4*)&Xs[bb * IDIM + 0];
        const float4 x1 = *(const float4*)&Xs[bb * IDIM + 4];
        const float4 x2 = *(const float4*)&Xs[bb * IDIM + 8];
        const float4 x3 = *(const float4*)&Xs[bb * IDIM + 12];
        float a0 = x0.x * W[0], a1 = x0.y * W[1], a2 = x0.z * W[2], a3 = x0.w * W[3];
        a0 = fmaf(x1.x, W[4], a0);  a1 = fmaf(x1.y, W[5], a1);
        a2 = fmaf(x1.z, W[6], a2);  a3 = fmaf(x1.w, W[7], a3);
        a0 = fmaf(x2.x, W[8], a0);  a1 = fmaf(x2.y, W[9], a1);
        a2 = fmaf(x2.z, W[10], a2); a3 = fmaf(x2.w, W[11], a3);
        a0 = fmaf(x3.x, W[12], a0); a1 = fmaf(x3.y, W[13], a1);
        a2 = fmaf(x3.z, W[14], a2); a3 = fmaf(x3.w, W[15], a3);
        float val = (a0 + a1) + (a2 + a3);
        __nv_bfloat16 hi = __float2bfloat16_rn(val);
        float lof = val - __bfloat162float(hi);
        __nv_bfloat16 lo = __float2bfloat16_rn(lof);
        size_t idx = ((size_t)bb * NCAPS + c) * DOUT + o;
        g_hi[idx] = hi;
        g_lo[idx] = lo;
    }
}

// ---------------------------------------------------------------------------
// Stage 2: C_b = U_b^T U_b via mma.sync bf16 2-way split (hh + hl + lh).
// 64x64 triangular tiles, grid (10, 64), block 128 (4 warps), Kc=32 dbuf.
// ---------------------------------------------------------------------------
__device__ __forceinline__ void cp16b(u32 saddr, const void* g) {
    asm volatile("cp.async.ca.shared.global [%0], [%1], 16;\n" :: "r"(saddr), "l"(g));
}

#define PANEL_B 9216u        // 2 bufs * 32 rows * 144 bytes
#define BUF_B   4608u        // 32 rows * 144 bytes
#define ROW_B   144u         // 72 bf16 pitch

__global__ __launch_bounds__(128) void k_syrk_mma() {
    const int p = blockIdx.x;
    const int b = blockIdx.y;

    int dt, et;
    if (p < 1)      { dt = 0; et = 0; }
    else if (p < 3) { dt = 1; et = p - 1; }
    else if (p < 6) { dt = 2; et = p - 3; }
    else            { dt = 3; et = p - 6; }

    const int tid = threadIdx.x;
    const int wid = tid >> 5, lane = tid & 31;
    const int dbase = dt * 64, ebase = et * 64;

    __shared__ __align__(16) char smem[4 * PANEL_B];   // 36864 B
    const u32 sbase = (u32)__cvta_generic_to_shared(smem);

    const __nv_bfloat16* bh = g_hi + (size_t)b * NCAPS * DOUT;
    const __nv_bfloat16* bl = g_lo + (size_t)b * NCAPS * DOUT;

    float acc[8][4];
#pragma unroll
    for (int j = 0; j < 8; ++j)
#pragma unroll
        for (int q = 0; q < 4; ++q) acc[j][q] = 0.0f;

    const int grp = lane >> 3, li = lane & 7;
    const int o0 = wid * 16;
    const u32 aRel = (u32)((li + ((grp >> 1) & 1) * 8) * ROW_B + (o0 + (grp & 1) * 8) * 2);
    const u32 bRel = (u32)((li + (grp & 1) * 8) * ROW_B + (((grp >> 1) & 1) * 8) * 2);

    auto load_chunk = [&](int buf, int kc) {
        const __nv_bfloat16* srcs[4] = { bh + dbase, bl + dbase, bh + ebase, bl + ebase };
#pragma unroll
        for (int pp = 0; pp < 4; ++pp) {
#pragma unroll
            for (int i = 0; i < 2; ++i) {
                int idx = i * 128 + tid;
                int row = idx >> 3, ch = idx & 7;
                u32 dst = sbase + pp * PANEL_B + (u32)buf * BUF_B + (u32)row * ROW_B + (u32)ch * 16u;
                cp16b(dst, srcs[pp] + (size_t)(kc + row) * DOUT + ch * 8);
            }
        }
    };

    load_chunk(0, 0);
    asm volatile("cp.async.commit_group;\n");

    const int NCH = NCAPS / 32;   // 64
    for (int chunk = 0; chunk < NCH; ++chunk) {
        const int buf = chunk & 1;
        if (chunk + 1 < NCH) {
            load_chunk(buf ^ 1, (chunk + 1) * 32);
            asm volatile("cp.async.commit_group;\n");
            asm volatile("cp.async.wait_group 1;\n");
        } else {
            asm volatile("cp.async.wait_group 0;\n");
        }
        __syncthreads();

#pragma unroll
        for (int ss = 0; ss < 2; ++ss) {
            const u32 kbyte = (u32)buf * BUF_B + (u32)ss * 16u * ROW_B;
            u32 a_h[4], a_l[4];
            asm volatile("ldmatrix.sync.aligned.m8n8.x4.trans.shared.b16 {%0,%1,%2,%3}, [%4];"
                : "=r"(a_h[0]), "=r"(a_h[1]), "=r"(a_h[2]), "=r"(a_h[3])
                : "r"(sbase + 0 * PANEL_B + kbyte + aRel));
            asm volatile("ldmatrix.sync.aligned.m8n8.x4.trans.shared.b16 {%0,%1,%2,%3}, [%4];"
                : "=r"(a_l[0]), "=r"(a_l[1]), "=r"(a_l[2]), "=r"(a_l[3])
                : "r"(sbase + 1 * PANEL_B + kbyte + aRel));

#pragma unroll
            for (int nb = 0; nb < 4; ++nb) {
                u32 bhf[4], blf[4];
                u32 bAddr = sbase + 2 * PANEL_B + kbyte + bRel + (u32)nb * 32u;
                asm volatile("ldmatrix.sync.aligned.m8n8.x4.trans.shared.b16 {%0,%1,%2,%3}, [%4];"
                    : "=r"(bhf[0]), "=r"(bhf[1]), "=r"(bhf[2]), "=r"(bhf[3])
                    : "r"(bAddr));
                asm volatile("ldmatrix.sync.aligned.m8n8.x4.trans.shared.b16 {%0,%1,%2,%3}, [%4];"
                    : "=r"(blf[0]), "=r"(blf[1]), "=r"(blf[2]), "=r"(blf[3])
                    : "r"(bAddr + PANEL_B));

#define MMA4(C, A, B0, B1)                                                      \
    asm volatile("mma.sync.aligned.m16n8k16.row.col.f32.bf16.bf16.f32 "         \
                 "{%0,%1,%2,%3},{%4,%5,%6,%7},{%8,%9},{%0,%1,%2,%3};"           \
                 : "+f"(C[0]), "+f"(C[1]), "+f"(C[2]), "+f"(C[3])               \
                 : "r"(A[0]), "r"(A[1]), "r"(A[2]), "r"(A[3]), "r"(B0), "r"(B1))

                MMA4(acc[2 * nb],     a_h, bhf[0], bhf[1]);
                MMA4(acc[2 * nb + 1], a_h, bhf[2], bhf[3]);
                MMA4(acc[2 * nb],     a_h, blf[0], blf[1]);
                MMA4(acc[2 * nb + 1], a_h, blf[2], blf[3]);
                MMA4(acc[2 * nb],     a_l, bhf[0], bhf[1]);
                MMA4(acc[2 * nb + 1], a_l, bhf[2], bhf[3]);
#undef MMA4
            }
        }
        __syncthreads();
    }

    float* Cb = g_C + (size_t)b * DOUT * DOUT;
    const int r0 = dbase + wid * 16 + (lane >> 2);
    const int c0 = ebase + (lane & 3) * 2;
#pragma unroll
    for (int j = 0; j < 8; ++j) {
        int e = c0 + 8 * j;
        *(float2*)&Cb[(size_t)r0 * DOUT + e]       = make_float2(acc[j][0], acc[j][1]);
        *(float2*)&Cb[(size_t)(r0 + 8) * DOUT + e] = make_float2(acc[j][2], acc[j][3]);
    }
}

// ---------------------------------------------------------------------------
// Stage 3: top eigenvector via Chebyshev. 512 threads, 36 swizzled 32x32
// blocks, 64 conflict-free pass-units. Schedule: 2 warmups, eps0=5e-3
// (near typical spectral gap), decay 0.6, floor 8e-4, tol 8e-6.
// ---------------------------------------------------------------------------
#define NBLK 36
#define BLK_FLOATS 1024
#define NW 16
#define Y2S_STRIDE 264
#define EIG_SMEM_FLOATS (NBLK * BLK_FLOATS + 2 * 256 + 64 + NW * Y2S_STRIDE)
#define EIG_SMEM_BYTES (EIG_SMEM_FLOATS * 4)

__device__ const unsigned char SB_R[NBLK] = {
    0, 1,1, 2,2,2, 3,3,3,3, 4,4,4,4,4, 5,5,5,5,5,5,
    6,6,6,6,6,6,6, 7,7,7,7,7,7,7,7 };
__device__ const unsigned char SB_C[NBLK] = {
    0, 0,1, 0,1,2, 0,1,2,3, 0,1,2,3,4, 0,1,2,3,4,5,
    0,1,2,3,4,5,6, 0,1,2,3,4,5,6,7 };

__device__ const unsigned char UNITS[64] = {
    0, 32, 36, 64, 68, 72, 96, 100, 104, 108, 128, 132, 136, 140, 144, 160,
    164, 168, 172, 176, 180, 192, 196, 200, 204, 208, 212, 216, 224, 228, 232, 236,
    240, 244, 248, 252,
    33, 65, 69, 97, 101, 105, 129, 133, 137, 141, 161, 165, 169, 173, 177, 193,
    197, 201, 205, 209, 213, 225, 229, 233, 237, 241, 245, 249 };

__device__ __forceinline__ int sw_off(int r, int c) {
    return r * 32 + ((((c >> 2) ^ (r & 7)) << 2) | (c & 3));
}

__device__ __forceinline__ float warpSum(float v) {
#pragma unroll
    for (int o = 16; o; o >>= 1) v += __shfl_xor_sync(0xffffffffu, v, o);
    return v;
}
__device__ float blockSum(float val, float* red, int t) {
    val = warpSum(val);
    if ((t & 31) == 0) red[t >> 5] = val;
    __syncthreads();
    if (t < 32) {
        float x = (t < NW) ? red[t] : 0.0f;
        x = warpSum(x);
        if (t == 0) red[32] = x;
    }
    __syncthreads();
    float r = red[32];
    __syncthreads();
    return r;
}
__device__ float blockMax(float val, float* red, int t) {
#pragma unroll
    for (int o = 16; o; o >>= 1) val = fmaxf(val, __shfl_xor_sync(0xffffffffu, val, o));
    if ((t & 31) == 0) red[t >> 5] = val;
    __syncthreads();
    if (t < 32) {
        float x = (t < NW) ? red[t] : -1.0f;
#pragma unroll
        for (int o = 16; o; o >>= 1) x = fmaxf(x, __shfl_xor_sync(0xffffffffu, x, o));
        if (t == 0) red[32] = x;
    }
    __syncthreads();
    float r = red[32];
    __syncthreads();
    return r;
}
__device__ int blockMinInt(int val, float* redf, int t) {
    int* red = (int*)redf;
#pragma unroll
    for (int o = 16; o; o >>= 1) val = min(val, __shfl_xor_sync(0xffffffffu, val, o));
    if ((t & 31) == 0) red[t >> 5] = val;
    __syncthreads();
    if (t < 32) {
        int x = (t < NW) ? red[t] : 0x7fffffff;
#pragma unroll
        for (int o = 16; o; o >>= 1) x = min(x, __shfl_xor_sync(0xffffffffu, x, o));
        if (t == 0) red[32] = x;
    }
    __syncthreads();
    int r = red[32];
    __syncthreads();
    return r;
}

__device__ __forceinline__ float symMatvecB(const float* __restrict__ blocks,
                                            const float* __restrict__ v,
                                            float* __restrict__ y2s,
                                            int t) {
    const int l = t & 31, w = t >> 5;
    float* myp = y2s + w * Y2S_STRIDE;

#pragma unroll
    for (int k = 0; k < 8; ++k) myp[32 * k + l] = 0.0f;

#pragma unroll
    for (int q = 0; q < 4; ++q) {
        const int enc = UNITS[w + 16 * q];
        const int R = enc >> 5, C = (enc >> 2) & 7, type = enc & 1;
        const float* blk = blocks + (R * (R + 1) / 2 + C) * BLK_FLOATS;
        if (type == 0) {
            const float4* vq = (const float4*)(v + 32 * C);
            const float* bl = blk + l * 32;
            const int lx = l & 7;
            float a0 = 0.f, a1 = 0.f, a2 = 0.f, a3 = 0.f;
#pragma unroll
            for (int qq = 0; qq < 8; ++qq) {
                float4 a = *(const float4*)(bl + ((qq ^ lx) << 2));
                float4 vv = vq[qq];
                a0 = fmaf(a.x, vv.x, a0);
                a1 = fmaf(a.y, vv.y, a1);
                a2 = fmaf(a.z, vv.z, a2);
                a3 = fmaf(a.w, vv.w, a3);
            }
            myp[32 * R + l] += (a0 + a1) + (a2 + a3);
        } else {
            const int hi = l >> 2, lo = l & 3;
            const float* vb = v + 32 * R;
            float a0 = 0.f, a1 = 0.f, a2 = 0.f, a3 = 0.f;
#pragma unroll
            for (int rq = 0; rq < 8; ++rq) {
                float4 vv = *(const float4*)(vb + 4 * rq);
                const float* base = blk + rq * 128;
                a0 = fmaf(base[       (((hi ^ ((4 * rq)     & 7)) << 2) | lo)], vv.x, a0);
                a1 = fmaf(base[32  + (((hi ^ ((4 * rq + 1) & 7)) << 2) | lo)], vv.y, a1);
                a2 = fmaf(base[64  + (((hi ^ ((4 * rq + 2) & 7)) << 2) | lo)], vv.z, a2);
                a3 = fmaf(base[96  + (((hi ^ ((4 * rq + 3) & 7)) << 2) | lo)], vv.w, a3);
            }
            myp[32 * C + l] += (a0 + a1) + (a2 + a3);
        }
    }
    __syncthreads();

    float y = 0.f;
    if (t < 256) {
#pragma unroll
        for (int ww = 0; ww < NW; ++ww) y += y2s[ww * Y2S_STRIDE + t];
    }
    return y;
}

__global__ __launch_bounds__(512, 1) void k_eig(float* __restrict__ out) {
    extern __shared__ __align__(16) float sm[];
    float* blocks = sm;                          // 36 * 1024
    float* v   = sm + NBLK * BLK_FLOATS;         // 256
    float* vp  = v + 256;                        // 256
    float* red = vp + 256;                       // 64
    float* y2s = red + 64;                       // 16 * 264

    const int b = blockIdx.x;
    const int t = threadIdx.x;
    const bool act = (t < 256);
    const float* Cb = g_C + (size_t)b * DOUT * DOUT;

    for (int s = 0; s < NBLK; ++s) {
        const int R = SB_R[s], C = SB_C[s];
        float* dst = blocks + s * BLK_FLOATS;
#pragma unroll
        for (int k = 0; k < 2; ++k) {
            int idx = k * 512 + t;
            int r = idx >> 5, c = idx & 31;
            float val;
            if (R > C || c <= r) val = Cb[(32 * R + r) * DOUT + 32 * C + c];
            else                 val = Cb[(32 * C + c) * DOUT + 32 * R + r];
            dst[sw_off(r, c)] = val;
        }
    }
    if (act) v[t] = Cb[t * DOUT];
    __syncthreads();

    {
        float n2 = blockSum(act ? v[t] * v[t] : 0.0f, red, t);
        if (act) v[t] *= rsqrtf(fmaxf(n2, 1e-30f));
    }
    __syncthreads();

    // Warm-up power iterations (seed rho)
    for (int it = 0; it < 2; ++it) {
        float s = symMatvecB(blocks, v, y2s, t);
        float n2 = blockSum(s * s, red, t);
        if (act) v[t] = s * rsqrtf(fmaxf(n2, 1e-30f));
        __syncthreads();
    }

    // Chebyshev on [0, (1-eps)*rho], residual exit
    float eps = 5e-3f;
    float r2prev = 1e30f;
    for (int outer = 0; outer < 48; ++outer) {
        float s = symMatvecB(blocks, v, y2s, t);
        float rho = blockSum(act ? v[t] * s : 0.0f, red, t);
        float d = act ? (s - rho * v[t]) : 0.0f;
        float r2 = blockSum(d * d, red, t);
        float tol = 8e-6f * rho;
        if (r2 < tol * tol) break;
        if (r2 > 0.3f * r2prev) eps = fmaxf(eps * 0.6f, 8e-4f);
        r2prev = r2;

        const float inv2 = 2.0f / (rho * (1.0f - eps));
        if (act) {
            vp[t] = v[t];
            v[t] = inv2 * s - v[t];
        }
        __syncthreads();
        for (int m = 0; m < 16; ++m) {
            float z = symMatvecB(blocks, v, y2s, t);
            if (act) {
                float vn = 2.0f * inv2 * z - 2.0f * v[t] - vp[t];
                vp[t] = v[t];
                v[t] = vn;
            }
            __syncthreads();
        }
        float n2 = blockSum(act ? v[t] * v[t] : 0.0f, red, t);
        if (act) v[t] *= rsqrtf(fmaxf(n2, 1e-30f));
        __syncthreads();
    }

    {
        float n2 = blockSum(act ? v[t] * v[t] : 0.0f, red, t);
        if (act) v[t] *= (1.0f / sqrtf(fmaxf(n2, 1e-30f)));
        __syncthreads();
    }

    float av = act ? fabsf(v[t]) : -1.0f;
    float mx = blockMax(av, red, t);
    int idx = (act && av == mx) ? t : 1024;
    int imin = blockMinInt(idx, red, t);
    if (t == imin) red[41] = (v[t] < 0.0f) ? -1.0f : 1.0f;
    __syncthreads();
    if (act) out[b * 256 + t] = v[t] * red[41];
}

// ---------------------------------------------------------------------------
extern "C" void kernel_launch(void* const* d_in, const int* in_sizes, int n_in,
                              void* d_out, int out_size) {
    const float* x = (const float*)d_in[0];
    const float* w = (const float*)d_in[1];
    float* out = (float*)d_out;

    cudaFuncSetAttribute(k_eig, cudaFuncAttributeMaxDynamicSharedMemorySize,
                         EIG_SMEM_BYTES);

    k_u<<<NCAPS, 256>>>(x, w);
    k_syrk_mma<<<dim3(10, BATCH), 128>>>();
    k_eig<<<BATCH, 512, EIG_SMEM_BYTES>>>(out);
}

// round 16
// speedup vs baseline: 1.6861x; 1.0382x over previous
#include <cuda_runtime.h>
#include <cuda_bf16.h>
#include <cstdint>
#include <math.h>

#define BATCH 64
#define NCAPS 2048
#define IDIM 16
#define DOUT 256

typedef unsigned int u32;
typedef unsigned long long u64;

__device__ __nv_bfloat16 g_hi[(size_t)BATCH * NCAPS * DOUT];  // 67 MB [b][c][o]
__device__ __nv_bfloat16 g_lo[(size_t)BATCH * NCAPS * DOUT];  // 67 MB [b][c][o]
__device__ float g_C[(size_t)BATCH * DOUT * DOUT];            // 16 MB

// ---------------------------------------------------------------------------
// Stage 1: u[b,c,o] = sum_i x[b,c,i] * w[c,i,o]  -> bf16 hi/lo split
// ---------------------------------------------------------------------------
__global__ void k_u(const float* __restrict__ x, const float* __restrict__ w) {
    const int c = blockIdx.x;
    const int o = threadIdx.x;

    __shared__ __align__(16) float Xs[BATCH * IDIM];

    float W[IDIM];
#pragma unroll
    for (int i = 0; i < IDIM; ++i)
        W[i] = w[((size_t)c * IDIM + i) * DOUT + o];

    for (int l = o; l < BATCH * IDIM; l += 256) {
        int bb = l >> 4, ii = l & 15;
        Xs[l] = x[((size_t)bb * NCAPS + c) * IDIM + ii];
    }
    __syncthreads();

    for (int bb = 0; bb < BATCH; ++bb) {
        const float4 x0 = *(const float4*)&Xs[bb * IDIM + 0];
        const float4 x1 = *(const float4*)&Xs[bb * IDIM + 4];
        const float4 x2 = *(const float4*)&Xs[bb * IDIM + 8];
        const float4 x3 = *(const float4*)&Xs[bb * IDIM + 12];
        float a0 = x0.x * W[0], a1 = x0.y * W[1], a2 = x0.z * W[2], a3 = x0.w * W[3];
        a0 = fmaf(x1.x, W[4], a0);  a1 = fmaf(x1.y, W[5], a1);
        a2 = fmaf(x1.z, W[6], a2);  a3 = fmaf(x1.w, W[7], a3);
        a0 = fmaf(x2.x, W[8], a0);  a1 = fmaf(x2.y, W[9], a1);
        a2 = fmaf(x2.z, W[10], a2); a3 = fmaf(x2.w, W[11], a3);
        a0 = fmaf(x3.x, W[12], a0); a1 = fmaf(x3.y, W[13], a1);
        a2 = fmaf(x3.z, W[14], a2); a3 = fmaf(x3.w, W[15], a3);
        float val = (a0 + a1) + (a2 + a3);
        __nv_bfloat16 hi = __float2bfloat16_rn(val);
        float lof = val - __bfloat162float(hi);
        __nv_bfloat16 lo = __float2bfloat16_rn(lof);
        size_t idx = ((size_t)bb * NCAPS + c) * DOUT + o;
        g_hi[idx] = hi;
        g_lo[idx] = lo;
    }
}

// ---------------------------------------------------------------------------
// Stage 2: C_b = U_b^T U_b via mma.sync bf16 2-way split (hh + hl + lh).
// 64x64 triangular tiles, grid (10, 64), block 128 (4 warps), Kc=32 dbuf.
// ---------------------------------------------------------------------------
__device__ __forceinline__ void cp16b(u32 saddr, const void* g) {
    asm volatile("cp.async.ca.shared.global [%0], [%1], 16;\n" :: "r"(saddr), "l"(g));
}

#define PANEL_B 9216u        // 2 bufs * 32 rows * 144 bytes
#define BUF_B   4608u        // 32 rows * 144 bytes
#define ROW_B   144u         // 72 bf16 pitch

__global__ __launch_bounds__(128) void k_syrk_mma() {
    const int p = blockIdx.x;
    const int b = blockIdx.y;

    int dt, et;
    if (p < 1)      { dt = 0; et = 0; }
    else if (p < 3) { dt = 1; et = p - 1; }
    else if (p < 6) { dt = 2; et = p - 3; }
    else            { dt = 3; et = p - 6; }

    const int tid = threadIdx.x;
    const int wid = tid >> 5, lane = tid & 31;
    const int dbase = dt * 64, ebase = et * 64;

    __shared__ __align__(16) char smem[4 * PANEL_B];   // 36864 B
    const u32 sbase = (u32)__cvta_generic_to_shared(smem);

    const __nv_bfloat16* bh = g_hi + (size_t)b * NCAPS * DOUT;
    const __nv_bfloat16* bl = g_lo + (size_t)b * NCAPS * DOUT;

    float acc[8][4];
#pragma unroll
    for (int j = 0; j < 8; ++j)
#pragma unroll
        for (int q = 0; q < 4; ++q) acc[j][q] = 0.0f;

    const int grp = lane >> 3, li = lane & 7;
    const int o0 = wid * 16;
    const u32 aRel = (u32)((li + ((grp >> 1) & 1) * 8) * ROW_B + (o0 + (grp & 1) * 8) * 2);
    const u32 bRel = (u32)((li + (grp & 1) * 8) * ROW_B + (((grp >> 1) & 1) * 8) * 2);

    auto load_chunk = [&](int buf, int kc) {
        const __nv_bfloat16* srcs[4] = { bh + dbase, bl + dbase, bh + ebase, bl + ebase };
#pragma unroll
        for (int pp = 0; pp < 4; ++pp) {
#pragma unroll
            for (int i = 0; i < 2; ++i) {
                int idx = i * 128 + tid;
                int row = idx >> 3, ch = idx & 7;
                u32 dst = sbase + pp * PANEL_B + (u32)buf * BUF_B + (u32)row * ROW_B + (u32)ch * 16u;
                cp16b(dst, srcs[pp] + (size_t)(kc + row) * DOUT + ch * 8);
            }
        }
    };

    load_chunk(0, 0);
    asm volatile("cp.async.commit_group;\n");

    const int NCH = NCAPS / 32;   // 64
    for (int chunk = 0; chunk < NCH; ++chunk) {
        const int buf = chunk & 1;
        if (chunk + 1 < NCH) {
            load_chunk(buf ^ 1, (chunk + 1) * 32);
            asm volatile("cp.async.commit_group;\n");
            asm volatile("cp.async.wait_group 1;\n");
        } else {
            asm volatile("cp.async.wait_group 0;\n");
        }
        __syncthreads();

#pragma unroll
        for (int ss = 0; ss < 2; ++ss) {
            const u32 kbyte = (u32)buf * BUF_B + (u32)ss * 16u * ROW_B;
            u32 a_h[4], a_l[4];
            asm volatile("ldmatrix.sync.aligned.m8n8.x4.trans.shared.b16 {%0,%1,%2,%3}, [%4];"
                : "=r"(a_h[0]), "=r"(a_h[1]), "=r"(a_h[2]), "=r"(a_h[3])
                : "r"(sbase + 0 * PANEL_B + kbyte + aRel));
            asm volatile("ldmatrix.sync.aligned.m8n8.x4.trans.shared.b16 {%0,%1,%2,%3}, [%4];"
                : "=r"(a_l[0]), "=r"(a_l[1]), "=r"(a_l[2]), "=r"(a_l[3])
                : "r"(sbase + 1 * PANEL_B + kbyte + aRel));

#pragma unroll
            for (int nb = 0; nb < 4; ++nb) {
                u32 bhf[4], blf[4];
                u32 bAddr = sbase + 2 * PANEL_B + kbyte + bRel + (u32)nb * 32u;
                asm volatile("ldmatrix.sync.aligned.m8n8.x4.trans.shared.b16 {%0,%1,%2,%3}, [%4];"
                    : "=r"(bhf[0]), "=r"(bhf[1]), "=r"(bhf[2]), "=r"(bhf[3])
                    : "r"(bAddr));
                asm volatile("ldmatrix.sync.aligned.m8n8.x4.trans.shared.b16 {%0,%1,%2,%3}, [%4];"
                    : "=r"(blf[0]), "=r"(blf[1]), "=r"(blf[2]), "=r"(blf[3])
                    : "r"(bAddr + PANEL_B));

#define MMA4(C, A, B0, B1)                                                      \
    asm volatile("mma.sync.aligned.m16n8k16.row.col.f32.bf16.bf16.f32 "         \
                 "{%0,%1,%2,%3},{%4,%5,%6,%7},{%8,%9},{%0,%1,%2,%3};"           \
                 : "+f"(C[0]), "+f"(C[1]), "+f"(C[2]), "+f"(C[3])               \
                 : "r"(A[0]), "r"(A[1]), "r"(A[2]), "r"(A[3]), "r"(B0), "r"(B1))

                MMA4(acc[2 * nb],     a_h, bhf[0], bhf[1]);
                MMA4(acc[2 * nb + 1], a_h, bhf[2], bhf[3]);
                MMA4(acc[2 * nb],     a_h, blf[0], blf[1]);
                MMA4(acc[2 * nb + 1], a_h, blf[2], blf[3]);
                MMA4(acc[2 * nb],     a_l, bhf[0], bhf[1]);
                MMA4(acc[2 * nb + 1], a_l, bhf[2], bhf[3]);
#undef MMA4
            }
        }
        __syncthreads();
    }

    float* Cb = g_C + (size_t)b * DOUT * DOUT;
    const int r0 = dbase + wid * 16 + (lane >> 2);
    const int c0 = ebase + (lane & 3) * 2;
#pragma unroll
    for (int j = 0; j < 8; ++j) {
        int e = c0 + 8 * j;
        *(float2*)&Cb[(size_t)r0 * DOUT + e]       = make_float2(acc[j][0], acc[j][1]);
        *(float2*)&Cb[(size_t)(r0 + 8) * DOUT + e] = make_float2(acc[j][2], acc[j][3]);
    }
}

// ---------------------------------------------------------------------------
// Stage 3: top eigenvector via Chebyshev. 512 threads, 36 swizzled 32x32
// blocks. Warp-pair-per-y-block matvec: warp pair (2g, 2g+1) owns y-block g;
// register accumulator per warp, 2-read gather. Schedule: 2 warmups,
// eps0=5e-3, decay 0.6, floor 8e-4, tol 8e-6.
// ---------------------------------------------------------------------------
#define NBLK 36
#define BLK_FLOATS 1024
#define NW 16
#define Y2S_STRIDE 33
#define EIG_SMEM_FLOATS (NBLK * BLK_FLOATS + 2 * 256 + 64 + NW * Y2S_STRIDE)
#define EIG_SMEM_BYTES (EIG_SMEM_FLOATS * 4)

__device__ const unsigned char SB_R[NBLK] = {
    0, 1,1, 2,2,2, 3,3,3,3, 4,4,4,4,4, 5,5,5,5,5,5,
    6,6,6,6,6,6,6, 7,7,7,7,7,7,7,7 };
__device__ const unsigned char SB_C[NBLK] = {
    0, 0,1, 0,1,2, 0,1,2,3, 0,1,2,3,4, 0,1,2,3,4,5,
    0,1,2,3,4,5,6, 0,1,2,3,4,5,6,7 };

__device__ __forceinline__ int sw_off(int r, int c) {
    return r * 32 + ((((c >> 2) ^ (r & 7)) << 2) | (c & 3));
}

__device__ __forceinline__ float warpSum(float v) {
#pragma unroll
    for (int o = 16; o; o >>= 1) v += __shfl_xor_sync(0xffffffffu, v, o);
    return v;
}
__device__ float blockSum(float val, float* red, int t) {
    val = warpSum(val);
    if ((t & 31) == 0) red[t >> 5] = val;
    __syncthreads();
    if (t < 32) {
        float x = (t < NW) ? red[t] : 0.0f;
        x = warpSum(x);
        if (t == 0) red[32] = x;
    }
    __syncthreads();
    float r = red[32];
    __syncthreads();
    return r;
}
__device__ float blockMax(float val, float* red, int t) {
#pragma unroll
    for (int o = 16; o; o >>= 1) val = fmaxf(val, __shfl_xor_sync(0xffffffffu, val, o));
    if ((t & 31) == 0) red[t >> 5] = val;
    __syncthreads();
    if (t < 32) {
        float x = (t < NW) ? red[t] : -1.0f;
#pragma unroll
        for (int o = 16; o; o >>= 1) x = fmaxf(x, __shfl_xor_sync(0xffffffffu, x, o));
        if (t == 0) red[32] = x;
    }
    __syncthreads();
    float r = red[32];
    __syncthreads();
    return r;
}
__device__ int blockMinInt(int val, float* redf, int t) {
    int* red = (int*)redf;
#pragma unroll
    for (int o = 16; o; o >>= 1) val = min(val, __shfl_xor_sync(0xffffffffu, val, o));
    if ((t & 31) == 0) red[t >> 5] = val;
    __syncthreads();
    if (t < 32) {
        int x = (t < NW) ? red[t] : 0x7fffffff;
#pragma unroll
        for (int o = 16; o; o >>= 1) x = min(x, __shfl_xor_sync(0xffffffffu, x, o));
        if (t == 0) red[32] = x;
    }
    __syncthreads();
    int r = red[32];
    __syncthreads();
    return r;
}

// y[t] = (C v)[t] for t<256. Warp pair (2g, 2g+1) computes y-block g:
// units ui=0..7 (half*4+u): ui<=g -> row-pass of block (g,ui);
// ui>g -> col-pass of block (ui,g). One internal __syncthreads.
__device__ __forceinline__ float symMatvecB(const float* __restrict__ blocks,
                                            const float* __restrict__ v,
                                            float* __restrict__ y2s,
                                            int t) {
    const int l = t & 31, w = t >> 5;
    const int g = w >> 1, half = w & 1;

    float accy = 0.0f;
#pragma unroll
    for (int u = 0; u < 4; ++u) {
        const int ui = half * 4 + u;
        if (ui <= g) {
            // row-pass: y[32g+l] += sum_c blk(g,ui)[l][c] * v[32ui+c]
            const float* blk = blocks + (g * (g + 1) / 2 + ui) * BLK_FLOATS;
            const float4* vq = (const float4*)(v + 32 * ui);
            const float* bl = blk + l * 32;
            const int lx = l & 7;
            float a0 = 0.f, a1 = 0.f, a2 = 0.f, a3 = 0.f;
#pragma unroll
            for (int qq = 0; qq < 8; ++qq) {
                float4 a = *(const float4*)(bl + ((qq ^ lx) << 2));
                float4 vv = vq[qq];
                a0 = fmaf(a.x, vv.x, a0);
                a1 = fmaf(a.y, vv.y, a1);
                a2 = fmaf(a.z, vv.z, a2);
                a3 = fmaf(a.w, vv.w, a3);
            }
            accy += (a0 + a1) + (a2 + a3);
        } else {
            // col-pass: y[32g+l] += sum_r blk(ui,g)[r][l] * v[32ui+r]
            const float* blk = blocks + (ui * (ui + 1) / 2 + g) * BLK_FLOATS;
            const int hi = l >> 2, lo = l & 3;
            const float* vb = v + 32 * ui;
            float a0 = 0.f, a1 = 0.f, a2 = 0.f, a3 = 0.f;
#pragma unroll
            for (int rq = 0; rq < 8; ++rq) {
                float4 vv = *(const float4*)(vb + 4 * rq);
                const float* base = blk + rq * 128;
                a0 = fmaf(base[       (((hi ^ ((4 * rq)     & 7)) << 2) | lo)], vv.x, a0);
                a1 = fmaf(base[32  + (((hi ^ ((4 * rq + 1) & 7)) << 2) | lo)], vv.y, a1);
                a2 = fmaf(base[64  + (((hi ^ ((4 * rq + 2) & 7)) << 2) | lo)], vv.z, a2);
                a3 = fmaf(base[96  + (((hi ^ ((4 * rq + 3) & 7)) << 2) | lo)], vv.w, a3);
            }
            accy += (a0 + a1) + (a2 + a3);
        }
    }
    y2s[w * Y2S_STRIDE + l] = accy;
    __syncthreads();

    float y = 0.f;
    if (t < 256) {
        const int gg = t >> 5, ll = t & 31;
        y = y2s[(2 * gg) * Y2S_STRIDE + ll] + y2s[(2 * gg + 1) * Y2S_STRIDE + ll];
    }
    return y;
}

__global__ __launch_bounds__(512, 1) void k_eig(float* __restrict__ out) {
    extern __shared__ __align__(16) float sm[];
    float* blocks = sm;                          // 36 * 1024
    float* v   = sm + NBLK * BLK_FLOATS;         // 256
    float* vp  = v + 256;                        // 256
    float* red = vp + 256;                       // 64
    float* y2s = red + 64;                       // 16 * 33

    const int b = blockIdx.x;
    const int t = threadIdx.x;
    const bool act = (t < 256);
    const float* Cb = g_C + (size_t)b * DOUT * DOUT;

    for (int s = 0; s < NBLK; ++s) {
        const int R = SB_R[s], C = SB_C[s];
        float* dst = blocks + s * BLK_FLOATS;
#pragma unroll
        for (int k = 0; k < 2; ++k) {
            int idx = k * 512 + t;
            int r = idx >> 5, c = idx & 31;
            float val;
            if (R > C || c <= r) val = Cb[(32 * R + r) * DOUT + 32 * C + c];
            else                 val = Cb[(32 * C + c) * DOUT + 32 * R + r];
            dst[sw_off(r, c)] = val;
        }
    }
    if (act) v[t] = Cb[t * DOUT];
    __syncthreads();

    {
        float n2 = blockSum(act ? v[t] * v[t] : 0.0f, red, t);
        if (act) v[t] *= rsqrtf(fmaxf(n2, 1e-30f));
    }
    __syncthreads();

    // Warm-up power iterations (seed rho)
    for (int it = 0; it < 2; ++it) {
        float s = symMatvecB(blocks, v, y2s, t);
        float n2 = blockSum(act ? s * s : 0.0f, red, t);
        if (act) v[t] = s * rsqrtf(fmaxf(n2, 1e-30f));
        __syncthreads();
    }

    // Chebyshev on [0, (1-eps)*rho], residual exit
    float eps = 5e-3f;
    float r2prev = 1e30f;
    for (int outer = 0; outer < 48; ++outer) {
        float s = symMatvecB(blocks, v, y2s, t);
        float rho = blockSum(act ? v[t] * s : 0.0f, red, t);
        float d = act ? (s - rho * v[t]) : 0.0f;
        float r2 = blockSum(d * d, red, t);
        float tol = 8e-6f * rho;
        if (r2 < tol * tol) break;
        if (r2 > 0.3f * r2prev) eps = fmaxf(eps * 0.6f, 8e-4f);
        r2prev = r2;

        const float inv2 = 2.0f / (rho * (1.0f - eps));
        if (act) {
            vp[t] = v[t];
            v[t] = inv2 * s - v[t];
        }
        __syncthreads();
        for (int m = 0; m < 16; ++m) {
            float z = symMatvecB(blocks, v, y2s, t);
            if (act) {
                float vn = 2.0f * inv2 * z - 2.0f * v[t] - vp[t];
                vp[t] = v[t];
                v[t] = vn;
            }
            __syncthreads();
        }
        float n2 = blockSum(act ? v[t] * v[t] : 0.0f, red, t);
        if (act) v[t] *= rsqrtf(fmaxf(n2, 1e-30f));
        __syncthreads();
    }

    {
        float n2 = blockSum(act ? v[t] * v[t] : 0.0f, red, t);
        if (act) v[t] *= (1.0f / sqrtf(fmaxf(n2, 1e-30f)));
        __syncthreads();
    }

    float av = act ? fabsf(v[t]) : -1.0f;
    float mx = blockMax(av, red, t);
    int idx = (act && av == mx) ? t : 1024;
    int imin = blockMinInt(idx, red, t);
    if (t == imin) red[41] = (v[t] < 0.0f) ? -1.0f : 1.0f;
    __syncthreads();
    if (act) out[b * 256 + t] = v[t] * red[41];
}

// ---------------------------------------------------------------------------
extern "C" void kernel_launch(void* const* d_in, const int* in_sizes, int n_in,
                              void* d_out, int out_size) {
    const float* x = (const float*)d_in[0];
    const float* w = (const float*)d_in[1];
    float* out = (float*)d_out;

    cudaFuncSetAttribute(k_eig, cudaFuncAttributeMaxDynamicSharedMemorySize,
                         EIG_SMEM_BYTES);

    k_u<<<NCAPS, 256>>>(x, w);
    k_syrk_mma<<<dim3(10, BATCH), 128>>>();
    k_eig<<<BATCH, 512, EIG_SMEM_BYTES>>>(out);
}